// round 12
// baseline (speedup 1.0000x reference)
#include <cuda_runtime.h>
#include <cuda_bf16.h>
#include <math.h>
#include <stdint.h>

#define NUM_H 24
#define LQ 1280
#define LK 2304

// ---------------- scratch (device globals; no allocations) ----------------
__device__ float g_q[4*24*1280*64];      // (B,H,LQ,64)
__device__ float g_k[4*24*2304*64];
__device__ float g_v[4*24*2304*64];
__device__ float g_ah[4*1024*1536];      // attention out, hidden part
__device__ float g_ae[4*256*1536];       // attention out, encoder part
__device__ float g_mq[6144], g_sq[6144], g_mk[6144], g_sk[6144];
__device__ float g_ps[96*4*64], g_pss[96*4*64];   // stats partials
// fragment-packed K/V for attention
__device__ uint4 g_kf[96*36*1024];
__device__ uint4 g_vf[96*36*1024];

// ---------------- bf16 helpers ----------------
__device__ __forceinline__ void split_pair(float x, float y, uint32_t &hi, uint32_t &lo){
    __nv_bfloat162 hv = __floats2bfloat162_rn(x, y);
    hi = *reinterpret_cast<uint32_t*>(&hv);
    float rx = x - __low2float(hv);
    float ry = y - __high2float(hv);
    __nv_bfloat162 lv = __floats2bfloat162_rn(rx, ry);
    lo = *reinterpret_cast<uint32_t*>(&lv);
}

__device__ __forceinline__ void mma16(float* c, const uint32_t* a, uint32_t b0, uint32_t b1){
    asm volatile("mma.sync.aligned.m16n8k16.row.col.f32.bf16.bf16.f32 "
        "{%0,%1,%2,%3},{%4,%5,%6,%7},{%8,%9},{%0,%1,%2,%3};"
        : "+f"(c[0]),"+f"(c[1]),"+f"(c[2]),"+f"(c[3])
        : "r"(a[0]),"r"(a[1]),"r"(a[2]),"r"(a[3]),"r"(b0),"r"(b1));
}

__device__ __forceinline__ void ldsm4(uint32_t* r, uint32_t addr){
    asm volatile("ldmatrix.sync.aligned.m8n8.x4.shared.b16 {%0,%1,%2,%3}, [%4];"
        : "=r"(r[0]),"=r"(r[1]),"=r"(r[2]),"=r"(r[3]) : "r"(addr));
}

__device__ __forceinline__ void cp16(uint32_t saddr, const void* gptr){
    asm volatile("cp.async.cg.shared.global [%0], [%1], 16;" :: "r"(saddr), "l"(gptr));
}

// ================= split-bf16 GEMM: 128x128 tile, BK=32, 512 threads ========
// 2 CTAs/SM (64KB smem each, regs <=128): cross-CTA overlap hides stage/sync.
#define GBUF 8192
#define GEMM_SMEM (2*GBUF*4)   // 65536 B

__device__ __forceinline__ void gemm_core(
    const float* __restrict__ A, const float* __restrict__ W,
    const float* __restrict__ bias, float* __restrict__ out,
    int K, int N, int heads_mode, int S_rows, int L, int s_off,
    int row0, int col0, uint32_t* sm)
{
    const int tid = threadIdx.x, lane = tid & 31, wrp = tid >> 5;
    const int g = lane >> 2, t = lane & 3;
    const int wm = wrp >> 2, wn = wrp & 3;

    float acc[2][4][4];
    #pragma unroll
    for (int i=0;i<2;i++)
        #pragma unroll
        for (int j=0;j<4;j++)
            #pragma unroll
            for (int r=0;r<4;r++) acc[i][j][r]=0.f;

    const int am0 = tid >> 3;
    const int ak4 = tid & 7;
    const int bs  = tid >> 8;
    const int bt  = (tid >> 6) & 3;
    const int bn  = (tid & 63) * 2;

    const uint32_t sbase = (uint32_t)__cvta_generic_to_shared(sm);
    uint32_t a_off[2][2];
    #pragma unroll
    for (int mt=0; mt<2; mt++){
        int r = wm*32 + mt*16 + ((lane>>3)&1)*8 + (lane&7);
        int swz = (r>>1)&3;
        #pragma unroll
        for (int s=0; s<2; s++){
            int u = s*2 + (lane>>4);
            a_off[mt][s] = (uint32_t)(r*64 + ((u ^ swz)<<4));
        }
    }
    uint32_t b_slot[2][4];
    #pragma unroll
    for (int s=0; s<2; s++)
        #pragma unroll
        for (int nt=0; nt<4; nt++){
            int ntg = wn*4 + nt;
            int lp = ((g*4+t) ^ (g>>1)) ^ ((ntg&1)<<2);
            b_slot[s][nt] = (uint32_t)((s*16+ntg)*32 + lp);
        }

    float4 ra[2];
    float2 rb[4];
    const int nT = K >> 5;

#define LOADG(tk) { \
    const float* Ab = A + (size_t)row0 * K + (tk)*32; \
    ra[0] = *(const float4*)&Ab[(size_t)am0*K + ak4*4]; \
    ra[1] = *(const float4*)&Ab[(size_t)(am0+64)*K + ak4*4]; \
    const float* Wb = W + (size_t)((tk)*32 + bs*16 + 2*bt)*N + col0 + bn; \
    rb[0] = *(const float2*)Wb; \
    rb[1] = *(const float2*)(Wb + N); \
    rb[2] = *(const float2*)(Wb + 8*(size_t)N); \
    rb[3] = *(const float2*)(Wb + 9*(size_t)N); }

#define STOREB(buf) { \
    uint32_t* Ah = (buf); uint32_t* Al = (buf)+2048; \
    uint4* Bp = (uint4*)((buf)+4096); \
    _Pragma("unroll") \
    for (int i=0;i<2;i++){ \
        int r = am0 + i*64; \
        uint2 hv, lv; \
        split_pair(ra[i].x, ra[i].y, hv.x, lv.x); \
        split_pair(ra[i].z, ra[i].w, hv.y, lv.y); \
        int o = r*16 + (((ak4>>1) ^ ((r>>1)&3))<<2) + (ak4&1)*2; \
        *(uint2*)&Ah[o] = hv; *(uint2*)&Al[o] = lv; \
    } \
    { \
        uint4 w4; \
        split_pair(rb[0].x, rb[1].x, w4.x, w4.z); \
        split_pair(rb[2].x, rb[3].x, w4.y, w4.w); \
        int n0 = bn, ntg = n0>>3, gg = n0&7; \
        int lp = ((gg*4+bt) ^ (gg>>1)) ^ ((ntg&1)<<2); \
        Bp[(bs*16+ntg)*32 + lp] = w4; \
        split_pair(rb[0].y, rb[1].y, w4.x, w4.z); \
        split_pair(rb[2].y, rb[3].y, w4.y, w4.w); \
        int n1 = bn+1; ntg = n1>>3; gg = n1&7; \
        lp = ((gg*4+bt) ^ (gg>>1)) ^ ((ntg&1)<<2); \
        Bp[(bs*16+ntg)*32 + lp] = w4; \
    } }

    LOADG(0);
    STOREB(sm);
    __syncthreads();

    for (int tk=0; tk<nT; tk++){
        uint32_t* buf = sm + (tk&1)*GBUF;
        const uint32_t bufb = sbase + (uint32_t)(tk&1)*(GBUF*4);
        if (tk+1 < nT) LOADG(tk+1);
        const uint4* Bp = (const uint4*)(buf+4096);
        #pragma unroll
        for (int s=0;s<2;s++){
            uint32_t ah[2][4], al[2][4];
            #pragma unroll
            for (int mt=0;mt<2;mt++){
                ldsm4(ah[mt], bufb + a_off[mt][s]);
                ldsm4(al[mt], bufb + 8192u + a_off[mt][s]);
            }
            #pragma unroll
            for (int nt=0;nt<4;nt++){
                uint4 kw = Bp[b_slot[s][nt]];
                #pragma unroll
                for (int mt=0;mt<2;mt++){
                    mma16(acc[mt][nt], ah[mt], kw.x, kw.y);
                    mma16(acc[mt][nt], ah[mt], kw.z, kw.w);
                    mma16(acc[mt][nt], al[mt], kw.x, kw.y);
                }
            }
        }
        if (tk+1 < nT) { STOREB(sm + ((tk+1)&1)*GBUF); }
        __syncthreads();
    }

    #pragma unroll
    for (int mt=0;mt<2;mt++){
        int m0r = row0 + wm*32 + mt*16 + g;
        #pragma unroll
        for (int nt=0;nt<4;nt++){
            int c = col0 + wn*32 + nt*8 + t*2;
            float b0v = bias[c], b1v = bias[c+1];
            float2 v0 = make_float2(acc[mt][nt][0]+b0v, acc[mt][nt][1]+b1v);
            float2 v1 = make_float2(acc[mt][nt][2]+b0v, acc[mt][nt][3]+b1v);
            if (!heads_mode){
                *(float2*)&out[(size_t)m0r*N + c]     = v0;
                *(float2*)&out[(size_t)(m0r+8)*N + c] = v1;
            } else {
                int hh = c >> 6, hd = c & 63;
                int bb = m0r / S_rows, ss = m0r - bb*S_rows;
                *(float2*)&out[((size_t)(bb*NUM_H+hh)*L + s_off + ss)*64 + hd] = v0;
                int m1r = m0r + 8;
                int bb1 = m1r / S_rows, ss1 = m1r - bb1*S_rows;
                *(float2*)&out[((size_t)(bb1*NUM_H+hh)*L + s_off + ss1)*64 + hd] = v1;
            }
        }
    }
#undef LOADG
#undef STOREB
}

__global__ void __launch_bounds__(512, 2) gemm_qkv(
    const float* __restrict__ A,
    const float* __restrict__ W0, const float* __restrict__ W1, const float* __restrict__ W2,
    const float* __restrict__ b0, const float* __restrict__ b1, const float* __restrict__ b2,
    float* __restrict__ o0, float* __restrict__ o1, float* __restrict__ o2,
    int K, int N, int S_rows, int L0, int L1, int L2,
    int soff0, int soff1, int soff2)
{
    extern __shared__ uint32_t sm[];
    const int z = blockIdx.z;
    const float* W = (z==0)? W0 : (z==1)? W1 : W2;
    const float* bi = (z==0)? b0 : (z==1)? b1 : b2;
    float* out = (z==0)? o0 : (z==1)? o1 : o2;
    int L = (z==0)? L0 : (z==1)? L1 : L2;
    int soff = (z==0)? soff0 : (z==1)? soff1 : soff2;
    gemm_core(A, W, bi, out, K, N, 1, S_rows, L, soff,
              blockIdx.y*128, blockIdx.x*128, sm);
}

__global__ void __launch_bounds__(512, 2) gemm_out(
    const float* __restrict__ A0, const float* __restrict__ A1,
    const float* __restrict__ W0, const float* __restrict__ W1,
    const float* __restrict__ b0, const float* __restrict__ b1,
    float* __restrict__ o0, float* __restrict__ o1,
    int K, int N)
{
    extern __shared__ uint32_t sm[];
    const int z = blockIdx.z;
    if (z == 1 && blockIdx.y >= 8) return;
    const float* A = (z==0)? A0 : A1;
    const float* W = (z==0)? W0 : W1;
    const float* bi = (z==0)? b0 : b1;
    float* out = (z==0)? o0 : o1;
    gemm_core(A, W, bi, out, K, N, 0, 0, 0, 0,
              blockIdx.y*128, blockIdx.x*128, sm);
}

// ---------------- two-phase stats: partials then finalize ----------------
__global__ void __launch_bounds__(256) stats_part(
    const float* __restrict__ buf, int L,
    float* __restrict__ ps, float* __restrict__ pss)
{
    const int bh = blockIdx.x, part = blockIdx.y;
    const int tx = threadIdx.x & 63;
    const int ty = threadIdx.x >> 6;
    const float* p = buf + (size_t)bh * L * 64;
    float s = 0.f, ss = 0.f;
    for (int i = part*256 + ty; i < part*256 + 256; i += 4) {
        float v = p[(size_t)i*64 + tx];
        s += v; ss += v*v;
    }
    __shared__ float sh1[4][64], sh2[4][64];
    sh1[ty][tx] = s; sh2[ty][tx] = ss;
    __syncthreads();
    if (ty == 0) {
        ps [(bh*4+part)*64 + tx] = sh1[0][tx]+sh1[1][tx]+sh1[2][tx]+sh1[3][tx];
        pss[(bh*4+part)*64 + tx] = sh2[0][tx]+sh2[1][tx]+sh2[2][tx]+sh2[3][tx];
    }
}

__global__ void __launch_bounds__(64) stats_fin(
    const float* __restrict__ ps, const float* __restrict__ pss,
    float* __restrict__ mean, float* __restrict__ stdev)
{
    const int bh = blockIdx.x, tx = threadIdx.x;
    float s = 0.f, ss = 0.f;
    #pragma unroll
    for (int p=0;p<4;p++){
        s  += ps [(bh*4+p)*64 + tx];
        ss += pss[(bh*4+p)*64 + tx];
    }
    float m = s * (1.0f/1024.0f);
    float var = (ss - 1024.0f*m*m) * (1.0f/1023.0f);
    mean[bh*64+tx]  = m;
    stdev[bh*64+tx] = sqrtf(var + 1e-5f);
}

// ---------------- AdaIN apply: q only (odd b) ----------------
__global__ void adain_q_kernel(
    float* __restrict__ q,
    const float* __restrict__ mq, const float* __restrict__ sq)
{
    const int idx = blockIdx.x * 256 + threadIdx.x;
    if (idx >= 2*24*1024*16) return;
    const int c  = (idx & 15) * 4;
    const int s  = (idx >> 4) & 1023;
    const int bhh = idx >> 14;
    const int bo = bhh / 24, h = bhh - bo*24;
    const int b  = 2*bo + 1;
    const int bh = b*24 + h;
    const int sbh = (b-1)*24 + h;

    const int ib = bh*64 + c, is = sbh*64 + c;
    float4 mb = *(const float4*)&mq[ib], sb = *(const float4*)&sq[ib];
    float4 ms = *(const float4*)&mq[is], so = *(const float4*)&sq[is];
    const size_t qi = ((size_t)bh*LQ + s)*64 + c;
    float4 x = *(const float4*)&q[qi];
    x.x = (x.x - mb.x)/sb.x*so.x + ms.x;
    x.y = (x.y - mb.y)/sb.y*so.y + ms.y;
    x.z = (x.z - mb.z)/sb.z*so.z + ms.z;
    x.w = (x.w - mb.w)/sb.w*so.w + ms.w;
    *(float4*)&q[qi] = x;
}

// ---------------- fused convert K: source remap + adain styling ----------
__global__ void __launch_bounds__(256) convert_k(
    const float* __restrict__ k,
    const float* __restrict__ mk, const float* __restrict__ sk,
    uint4* __restrict__ kf)
{
    const int kt = blockIdx.x, bh = blockIdx.y;
    const int b = bh / 24, h = bh - b*24;
    const bool odd = (b & 1);
    if (!odd && kt >= 16 && kt < 32) return;

    __shared__ float sK[64][65];
    __shared__ float pa[64], pc[64];
    const int tid = threadIdx.x;

    const float* src;
    bool style = false;
    if (kt < 16){ src = k + ((size_t)bh*LK + kt*64)*64; style = odd; }
    else if (kt < 32){ int sbh = (b-1)*24 + h; src = k + ((size_t)sbh*LK + (kt-16)*64)*64; }
    else { src = k + ((size_t)bh*LK + kt*64)*64; }

    if (style && tid < 64){
        int sbh = (b-1)*24 + h;
        float a = sk[sbh*64+tid] / sk[bh*64+tid];
        pa[tid] = a;
        pc[tid] = mk[sbh*64+tid] - mk[bh*64+tid]*a;
    }
    __syncthreads();
    #pragma unroll
    for (int i=0;i<16;i++){
        int e = tid + i*256;
        float x = src[e];
        if (style) x = fmaf(x, pa[e&63], pc[e&63]);
        sK[e>>6][e&63] = x;
    }
    __syncthreads();
    uint4* dst = kf + ((size_t)bh*36 + kt)*1024;
    #pragma unroll
    for (int i=0;i<4;i++){
        int slot = tid + i*256;
        int lane = slot & 31, nt = (slot>>5)&7, s = slot>>8;
        int g = lane>>2, t = lane&3;
        int kv = nt*8+g, d0 = 16*s+2*t;
        uint4 w4;
        split_pair(sK[kv][d0],   sK[kv][d0+1], w4.x, w4.z);
        split_pair(sK[kv][d0+8], sK[kv][d0+9], w4.y, w4.w);
        dst[slot] = w4;
    }
}

__global__ void __launch_bounds__(256) convert_v(
    const float* __restrict__ v, uint4* __restrict__ vf)
{
    const int kt = blockIdx.x, bh = blockIdx.y;
    const int b = bh / 24, h = bh - b*24;
    const bool odd = (b & 1);
    if (!odd && kt >= 16 && kt < 32) return;

    __shared__ float sV[64][65];
    const int tid = threadIdx.x;
    const float* src;
    if (kt < 32 && kt >= 16){ int sbh = (b-1)*24 + h; src = v + ((size_t)sbh*LK + (kt-16)*64)*64; }
    else { src = v + ((size_t)bh*LK + kt*64)*64; }

    #pragma unroll
    for (int i=0;i<16;i++){
        int e = tid + i*256;
        sV[e>>6][e&63] = src[e];
    }
    __syncthreads();
    uint4* dst = vf + ((size_t)bh*36 + kt)*1024;
    #pragma unroll
    for (int i=0;i<4;i++){
        int slot = tid + i*256;
        int lane = slot & 31, j = (slot>>5)&7, s2 = slot>>8;
        int g = lane>>2, t = lane&3;
        int d = j*8+g, r0 = 16*s2+2*t;
        uint4 w4;
        split_pair(sV[r0][d],   sV[r0+1][d], w4.x, w4.z);
        split_pair(sV[r0+8][d], sV[r0+9][d], w4.y, w4.w);
        dst[slot] = w4;
    }
}

// ================= split-bf16 flash attention, max-free softmax =============
#define AT_SMEM (2*2048*16)

__global__ void __launch_bounds__(256, 2) attn_bf3(
    const float* __restrict__ Q,
    const uint4* __restrict__ KF, const uint4* __restrict__ VF,
    float* __restrict__ outh, float* __restrict__ oute)
{
    extern __shared__ uint4 sm4[];
    const int tid = threadIdx.x, lane = tid & 31, w = tid >> 5;
    const int g = lane >> 2, t = lane & 3;
    const int qt = blockIdx.x, h = blockIdx.y, b = blockIdx.z;
    const bool odd = (b & 1);
    const int nkt = odd ? 36 : 20;
    const size_t bh = (size_t)b*NUM_H + h;
    const float* Qg = Q + (bh*LQ + (size_t)qt*128) * 64;
    const uint4* Kg = KF + bh*36*1024;
    const uint4* Vg = VF + bh*36*1024;
    const uint32_t smem_base = (uint32_t)__cvta_generic_to_shared(sm4);
    const float QSCALE = 0.125f * 1.44269504088896f;

#define KTOF(j_) ((odd || (j_) < 16) ? (j_) : (j_) + 16)
#define STAGE(kt_, buf_) { \
    uint32_t sb = smem_base + (buf_)*32768u; \
    const uint4* kp = Kg + (size_t)(kt_)*1024 + tid; \
    const uint4* vp = Vg + (size_t)(kt_)*1024 + tid; \
    _Pragma("unroll") \
    for (int i_=0;i_<4;i_++){ \
        cp16(sb + (uint32_t)(tid + i_*256)*16u,           kp + i_*256); \
        cp16(sb + 16384u + (uint32_t)(tid + i_*256)*16u,  vp + i_*256); \
    } \
    asm volatile("cp.async.commit_group;"); }

    STAGE(0, 0);

    uint32_t qh[4][4], ql[4][4];
    {
        const int r0 = w*16 + g;
        #pragma unroll
        for (int s=0;s<4;s++){
            int d0 = 16*s + 2*t;
            float2 x00 = *(const float2*)&Qg[(size_t)r0*64 + d0];
            float2 x10 = *(const float2*)&Qg[(size_t)(r0+8)*64 + d0];
            float2 x01 = *(const float2*)&Qg[(size_t)r0*64 + d0 + 8];
            float2 x11 = *(const float2*)&Qg[(size_t)(r0+8)*64 + d0 + 8];
            split_pair(x00.x*QSCALE, x00.y*QSCALE, qh[s][0], ql[s][0]);
            split_pair(x10.x*QSCALE, x10.y*QSCALE, qh[s][1], ql[s][1]);
            split_pair(x01.x*QSCALE, x01.y*QSCALE, qh[s][2], ql[s][2]);
            split_pair(x11.x*QSCALE, x11.y*QSCALE, qh[s][3], ql[s][3]);
        }
    }

    float o_[8][4];
    #pragma unroll
    for (int j=0;j<8;j++){ o_[j][0]=0.f; o_[j][1]=0.f; o_[j][2]=0.f; o_[j][3]=0.f; }
    float l0s=0.f, l1s=0.f;

    for (int jj=0; jj<nkt; jj++){
        asm volatile("cp.async.wait_group 0;");
        __syncthreads();
        if (jj+1 < nkt) { STAGE(KTOF(jj+1), (jj+1)&1); }

        const uint4* Kt = sm4 + (jj&1)*2048;
        const uint4* Vt = Kt + 1024;
        const float padd = (!odd && jj < 16) ? 1.0f : 0.0f;

        float s_[8][4];
        #pragma unroll
        for (int j=0;j<8;j++){ s_[j][0]=0.f; s_[j][1]=0.f; s_[j][2]=0.f; s_[j][3]=0.f; }
        #pragma unroll
        for (int s=0;s<4;s++)
            #pragma unroll
            for (int nt=0;nt<8;nt++){
                uint4 kw = Kt[(s*8+nt)*32 + lane];
                mma16(s_[nt], qh[s], kw.x, kw.y);
                mma16(s_[nt], qh[s], kw.z, kw.w);
                mma16(s_[nt], ql[s], kw.x, kw.y);
            }

        #pragma unroll
        for (int j=0;j<8;j++){
            s_[j][0]=exp2f(s_[j][0]+padd); s_[j][1]=exp2f(s_[j][1]+padd);
            s_[j][2]=exp2f(s_[j][2]+padd); s_[j][3]=exp2f(s_[j][3]+padd);
            l0s += s_[j][0]+s_[j][1];
            l1s += s_[j][2]+s_[j][3];
        }

        uint32_t ph[4][4], pl[4][4];
        #pragma unroll
        for (int s2=0;s2<4;s2++){
            split_pair(s_[2*s2][0],   s_[2*s2][1],   ph[s2][0], pl[s2][0]);
            split_pair(s_[2*s2][2],   s_[2*s2][3],   ph[s2][1], pl[s2][1]);
            split_pair(s_[2*s2+1][0], s_[2*s2+1][1], ph[s2][2], pl[s2][2]);
            split_pair(s_[2*s2+1][2], s_[2*s2+1][3], ph[s2][3], pl[s2][3]);
        }

        #pragma unroll
        for (int s2=0;s2<4;s2++)
            #pragma unroll
            for (int j=0;j<8;j++){
                uint4 vw = Vt[(s2*8+j)*32 + lane];
                mma16(o_[j], ph[s2], vw.x, vw.y);
                mma16(o_[j], ph[s2], vw.z, vw.w);
                mma16(o_[j], pl[s2], vw.x, vw.y);
            }
    }
#undef STAGE
#undef KTOF

    l0s += __shfl_xor_sync(0xffffffffu, l0s, 1);
    l0s += __shfl_xor_sync(0xffffffffu, l0s, 2);
    l1s += __shfl_xor_sync(0xffffffffu, l1s, 1);
    l1s += __shfl_xor_sync(0xffffffffu, l1s, 2);
    float inv0 = 1.0f / l0s, inv1 = 1.0f / l1s;
    int q0 = qt*128 + w*16 + g;
    #pragma unroll
    for (int j=0;j<8;j++){
        int c = h*64 + j*8 + t*2;
        float2 v0 = make_float2(o_[j][0]*inv0, o_[j][1]*inv0);
        float2 v1 = make_float2(o_[j][2]*inv1, o_[j][3]*inv1);
        if (q0 < 1024){
            *(float2*)&outh[((size_t)b*1024 + q0)*1536 + c]     = v0;
            *(float2*)&outh[((size_t)b*1024 + q0 + 8)*1536 + c] = v1;
        } else {
            *(float2*)&oute[((size_t)b*256 + q0-1024)*1536 + c]     = v0;
            *(float2*)&oute[((size_t)b*256 + q0-1024 + 8)*1536 + c] = v1;
        }
    }
}

// ---------------- launch ----------------
extern "C" void kernel_launch(void* const* d_in, const int* in_sizes, int n_in,
                              void* d_out, int out_size)
{
    (void)in_sizes; (void)n_in; (void)out_size;
    const float* hs  = (const float*)d_in[0];
    const float* ehs = (const float*)d_in[1];
    const float* wq  = (const float*)d_in[2];  const float* bq  = (const float*)d_in[3];
    const float* wk  = (const float*)d_in[4];  const float* bk  = (const float*)d_in[5];
    const float* wv  = (const float*)d_in[6];  const float* bv  = (const float*)d_in[7];
    const float* awq = (const float*)d_in[8];  const float* abq = (const float*)d_in[9];
    const float* awk = (const float*)d_in[10]; const float* abk = (const float*)d_in[11];
    const float* awv = (const float*)d_in[12]; const float* abv = (const float*)d_in[13];
    const float* wo  = (const float*)d_in[14]; const float* bo  = (const float*)d_in[15];
    const float* wao = (const float*)d_in[16]; const float* bao = (const float*)d_in[17];
    float* out = (float*)d_out;

    float *q, *k, *v, *ah, *ae, *mq, *sq, *mk, *sk, *ps, *pss;
    uint4 *kf, *vf;
    cudaGetSymbolAddress((void**)&q,  g_q);
    cudaGetSymbolAddress((void**)&k,  g_k);
    cudaGetSymbolAddress((void**)&v,  g_v);
    cudaGetSymbolAddress((void**)&ah, g_ah);
    cudaGetSymbolAddress((void**)&ae, g_ae);
    cudaGetSymbolAddress((void**)&mq, g_mq);
    cudaGetSymbolAddress((void**)&sq, g_sq);
    cudaGetSymbolAddress((void**)&mk, g_mk);
    cudaGetSymbolAddress((void**)&sk, g_sk);
    cudaGetSymbolAddress((void**)&ps, g_ps);
    cudaGetSymbolAddress((void**)&pss, g_pss);
    cudaGetSymbolAddress((void**)&kf, g_kf);
    cudaGetSymbolAddress((void**)&vf, g_vf);

    static int attr_set = 0;
    if (!attr_set) {
        cudaFuncSetAttribute(gemm_qkv, cudaFuncAttributeMaxDynamicSharedMemorySize, GEMM_SMEM);
        cudaFuncSetAttribute(gemm_out, cudaFuncAttributeMaxDynamicSharedMemorySize, GEMM_SMEM);
        cudaFuncSetAttribute(attn_bf3, cudaFuncAttributeMaxDynamicSharedMemorySize, AT_SMEM);
        attr_set = 1;
    }

    gemm_qkv<<<dim3(12, 32, 3), 512, GEMM_SMEM>>>(
        hs, wq, wk, wv, bq, bk, bv, q, k, v,
        1536, 1536, 1024, LQ, LK, LK, 0, 0, 0);
    gemm_qkv<<<dim3(12, 8, 3), 512, GEMM_SMEM>>>(
        ehs, awq, awk, awv, abq, abk, abv, q, k, v,
        1536, 1536, 256, LQ, LK, LK, 1024, 2048, 2048);

    stats_part<<<dim3(96, 4), 256>>>(q, LQ, ps, pss);
    stats_fin<<<96, 64>>>(ps, pss, mq, sq);
    stats_part<<<dim3(96, 4), 256>>>(k, LK, ps, pss);
    stats_fin<<<96, 64>>>(ps, pss, mk, sk);

    adain_q_kernel<<<3072, 256>>>(q, mq, sq);
    convert_k<<<dim3(36, 96), 256>>>(k, mk, sk, kf);
    convert_v<<<dim3(36, 96), 256>>>(v, vf);

    attn_bf3<<<dim3(10, 24, 4), 256, AT_SMEM>>>(q, kf, vf, ah, ae);

    gemm_out<<<dim3(12, 32, 2), 512, GEMM_SMEM>>>(
        ah, ae, wo, wao, bo, bao, out, out + (size_t)4096*1536, 1536, 1536);
}

// round 13
// speedup vs baseline: 1.2912x; 1.2912x over previous
#include <cuda_runtime.h>
#include <cuda_bf16.h>
#include <math.h>
#include <stdint.h>

#define NUM_H 24
#define LQ 1280
#define LK 2304

// ---------------- scratch (device globals; no allocations) ----------------
__device__ float g_q[4*24*1280*64];      // (B,H,LQ,64)
__device__ float g_k[4*24*2304*64];
__device__ float g_v[4*24*2304*64];
__device__ float g_mq[6144], g_sq[6144], g_mk[6144], g_sk[6144];
__device__ float g_ps[2*96*4*64], g_pss[2*96*4*64];   // stats partials (q,k)
// fragment-packed K/V for attention
__device__ uint4 g_kf[96*36*1024];
__device__ uint4 g_vf[96*36*1024];
// pre-split GEMM operands (u32 = bf16x2 over k-pairs)
__device__ uint32_t g_hsh[4096*768], g_hsl[4096*768];   // hidden_states
__device__ uint32_t g_esh[1024*768], g_esl[1024*768];   // encoder_hidden
__device__ uint32_t g_aoh[4096*768], g_aol[4096*768];   // attn out (hidden rows)
__device__ uint32_t g_eoh[1024*768], g_eol[1024*768];   // attn out (encoder rows)
// weights packed in B-fragment slot layout: [z][colblk 12][tk 48][1024 uint4]
__device__ uint4 g_wp[8*12*48*1024];

// ---------------- bf16 helpers ----------------
__device__ __forceinline__ void split_pair(float x, float y, uint32_t &hi, uint32_t &lo){
    __nv_bfloat162 hv = __floats2bfloat162_rn(x, y);
    hi = *reinterpret_cast<uint32_t*>(&hv);
    float rx = x - __low2float(hv);
    float ry = y - __high2float(hv);
    __nv_bfloat162 lv = __floats2bfloat162_rn(rx, ry);
    lo = *reinterpret_cast<uint32_t*>(&lv);
}

__device__ __forceinline__ void mma16(float* c, const uint32_t* a, uint32_t b0, uint32_t b1){
    asm volatile("mma.sync.aligned.m16n8k16.row.col.f32.bf16.bf16.f32 "
        "{%0,%1,%2,%3},{%4,%5,%6,%7},{%8,%9},{%0,%1,%2,%3};"
        : "+f"(c[0]),"+f"(c[1]),"+f"(c[2]),"+f"(c[3])
        : "r"(a[0]),"r"(a[1]),"r"(a[2]),"r"(a[3]),"r"(b0),"r"(b1));
}

__device__ __forceinline__ void ldsm4(uint32_t* r, uint32_t addr){
    asm volatile("ldmatrix.sync.aligned.m8n8.x4.shared.b16 {%0,%1,%2,%3}, [%4];"
        : "=r"(r[0]),"=r"(r[1]),"=r"(r[2]),"=r"(r[3]) : "r"(addr));
}

__device__ __forceinline__ void cp16(uint32_t saddr, const void* gptr){
    asm volatile("cp.async.cg.shared.global [%0], [%1], 16;" :: "r"(saddr), "l"(gptr));
}

// ================= split-bf16 GEMM, all-cp.async, 3-stage, occ-2 ============
// 128x128 tile, BK=32, 512 threads = 16 warps (4m x 4n), warp tile 32x32.
// Stage (32KB): Ah[8KB] Al[8KB] Bpk[16KB=1024 uint4 slots].
#define GSTG 32768u
#define GEMM_SMEM (3*32768)    // 98304 B

__device__ __forceinline__ void gemm_core(
    const uint32_t* __restrict__ Ah, const uint32_t* __restrict__ Al,  // [M][768]
    const uint4* __restrict__ Bp,                                      // [48][1024]
    const float* __restrict__ bias, float* __restrict__ out,
    int N, int heads_mode, int S_rows, int L, int s_off,
    int row0, int col0, uint32_t* sm)
{
    const int tid = threadIdx.x, lane = tid & 31, wrp = tid >> 5;
    const int g = lane >> 2, t = lane & 3;
    const int wm = wrp >> 2, wn = wrp & 3;

    float acc[2][4][4];
    #pragma unroll
    for (int i=0;i<2;i++)
        #pragma unroll
        for (int j=0;j<4;j++)
            #pragma unroll
            for (int r=0;r<4;r++) acc[i][j][r]=0.f;

    const uint32_t sbase = (uint32_t)__cvta_generic_to_shared(sm);
    uint32_t a_off[2][2];
    #pragma unroll
    for (int mt=0; mt<2; mt++){
        int r = wm*32 + mt*16 + ((lane>>3)&1)*8 + (lane&7);
        int swz = (r>>1)&3;
        #pragma unroll
        for (int s=0; s<2; s++){
            int u = s*2 + (lane>>4);
            a_off[mt][s] = (uint32_t)(r*64 + ((u ^ swz)<<4));
        }
    }
    uint32_t b_slot[2][4];
    #pragma unroll
    for (int s=0; s<2; s++)
        #pragma unroll
        for (int nt=0; nt<4; nt++){
            int ntg = wn*4 + nt;
            int lp = ((g*4+t) ^ (g>>1)) ^ ((ntg&1)<<2);
            b_slot[s][nt] = (uint32_t)((s*16+ntg)*32 + lp);
        }

    // staging maps (cp.async only)
    const int ar = tid >> 2;          // A row (two passes via +?) -> 512 thr cover 128r x 4u
    const int au = tid & 3;
    const uint32_t a_so = (uint32_t)(ar*64 + ((au ^ ((ar>>1)&3))<<4));
    const uint32_t a_gi = (uint32_t)(ar*768 + au*4);

#define STAGE(tk_, st_) { \
    uint32_t sb = sbase + (uint32_t)(st_)*GSTG; \
    const uint32_t kw = (uint32_t)(tk_)*16u; \
    cp16(sb + a_so,         Ah + (size_t)(row0+ar)*768 + kw + au*4); \
    cp16(sb + 8192u + a_so, Al + (size_t)(row0+ar)*768 + kw + au*4); \
    const uint4* bg = Bp + (size_t)(tk_)*1024 + tid; \
    cp16(sb + 16384u + (uint32_t)tid*16u,          bg); \
    cp16(sb + 16384u + (uint32_t)(tid+512)*16u,    bg + 512); \
    asm volatile("cp.async.commit_group;" ::: "memory"); }

    STAGE(0, 0);
    STAGE(1, 1);

    const int nT = 48;
    for (int tk=0; tk<nT; tk++){
        const int st = tk % 3;
        if (tk+1 < nT) asm volatile("cp.async.wait_group 1;" ::: "memory");
        else           asm volatile("cp.async.wait_group 0;" ::: "memory");
        __syncthreads();
        const uint32_t bufb = sbase + (uint32_t)st*GSTG;
        const uint4* Bs = (const uint4*)(sm + st*8192 + 4096);
        #pragma unroll
        for (int s=0;s<2;s++){
            uint32_t ah[2][4], al[2][4];
            #pragma unroll
            for (int mt=0;mt<2;mt++){
                ldsm4(ah[mt], bufb + a_off[mt][s]);
                ldsm4(al[mt], bufb + 8192u + a_off[mt][s]);
            }
            #pragma unroll
            for (int nt=0;nt<4;nt++){
                uint4 kw = Bs[b_slot[s][nt]];
                #pragma unroll
                for (int mt=0;mt<2;mt++){
                    mma16(acc[mt][nt], ah[mt], kw.x, kw.y);
                    mma16(acc[mt][nt], ah[mt], kw.z, kw.w);
                    mma16(acc[mt][nt], al[mt], kw.x, kw.y);
                }
            }
        }
        if (tk+2 < nT) { STAGE(tk+2, (tk+2)%3); }
    }
#undef STAGE

    #pragma unroll
    for (int mt=0;mt<2;mt++){
        int m0r = row0 + wm*32 + mt*16 + g;
        #pragma unroll
        for (int nt=0;nt<4;nt++){
            int c = col0 + wn*32 + nt*8 + t*2;
            float b0v = bias[c], b1v = bias[c+1];
            float2 v0 = make_float2(acc[mt][nt][0]+b0v, acc[mt][nt][1]+b1v);
            float2 v1 = make_float2(acc[mt][nt][2]+b0v, acc[mt][nt][3]+b1v);
            if (!heads_mode){
                *(float2*)&out[(size_t)m0r*N + c]     = v0;
                *(float2*)&out[(size_t)(m0r+8)*N + c] = v1;
            } else {
                int hh = c >> 6, hd = c & 63;
                int bb = m0r / S_rows, ss = m0r - bb*S_rows;
                *(float2*)&out[((size_t)(bb*NUM_H+hh)*L + s_off + ss)*64 + hd] = v0;
                int m1r = m0r + 8;
                int bb1 = m1r / S_rows, ss1 = m1r - bb1*S_rows;
                *(float2*)&out[((size_t)(bb1*NUM_H+hh)*L + s_off + ss1)*64 + hd] = v1;
            }
        }
    }
}

__global__ void __launch_bounds__(512, 2) gemm_qkv(
    const uint32_t* __restrict__ Ah, const uint32_t* __restrict__ Al,
    const uint4* __restrict__ WP, int widx0,
    const float* __restrict__ b0, const float* __restrict__ b1, const float* __restrict__ b2,
    float* __restrict__ o0, float* __restrict__ o1, float* __restrict__ o2,
    int S_rows, int L0, int L1, int L2, int soff0, int soff1, int soff2)
{
    extern __shared__ uint32_t sm[];
    const int z = blockIdx.z;
    const float* bi = (z==0)? b0 : (z==1)? b1 : b2;
    float* out = (z==0)? o0 : (z==1)? o1 : o2;
    int L = (z==0)? L0 : (z==1)? L1 : L2;
    int soff = (z==0)? soff0 : (z==1)? soff1 : soff2;
    const uint4* Bp = WP + (size_t)((widx0+z)*12 + blockIdx.x)*48*1024;
    gemm_core(Ah, Al, Bp, bi, out, 1536, 1, S_rows, L, soff,
              blockIdx.y*128, blockIdx.x*128, sm);
}

__global__ void __launch_bounds__(512, 2) gemm_out(
    const uint32_t* __restrict__ A0h, const uint32_t* __restrict__ A0l,
    const uint32_t* __restrict__ A1h, const uint32_t* __restrict__ A1l,
    const uint4* __restrict__ WP, int widx0,
    const float* __restrict__ b0, const float* __restrict__ b1,
    float* __restrict__ o0, float* __restrict__ o1)
{
    extern __shared__ uint32_t sm[];
    const int z = blockIdx.z;
    if (z == 1 && blockIdx.y >= 8) return;
    const uint4* Bp = WP + (size_t)((widx0+z)*12 + blockIdx.x)*48*1024;
    gemm_core((z==0)? A0h : A1h, (z==0)? A0l : A1l, Bp,
              (z==0)? b0 : b1, (z==0)? o0 : o1, 1536,
              0, 0, 0, 0, blockIdx.y*128, blockIdx.x*128, sm);
}

// ---------------- operand pre-conversion ----------------
__global__ void __launch_bounds__(256) conv_a(
    const float* __restrict__ x, uint32_t* __restrict__ hi, uint32_t* __restrict__ lo, int n4)
{
    int i = blockIdx.x*256 + threadIdx.x;
    if (i >= n4) return;
    float4 f = ((const float4*)x)[i];
    uint2 h, l;
    split_pair(f.x, f.y, h.x, l.x);
    split_pair(f.z, f.w, h.y, l.y);
    ((uint2*)hi)[i] = h; ((uint2*)lo)[i] = l;
}

// weights -> packed B-fragment slot layout (matches gemm b_slot consumption)
__global__ void __launch_bounds__(256) conv_wp(
    const float* w0, const float* w1, const float* w2, const float* w3,
    const float* w4, const float* w5, const float* w6, const float* w7,
    uint4* __restrict__ wp)
{
    __shared__ float sw[32][129];
    const int cb = blockIdx.x, tk = blockIdx.y, z = blockIdx.z;
    const float* W = (z==0)?w0:(z==1)?w1:(z==2)?w2:(z==3)?w3:(z==4)?w4:(z==5)?w5:(z==6)?w6:w7;
    const int tid = threadIdx.x;
    #pragma unroll
    for (int i=0;i<4;i++){
        int e = tid + i*256;
        int r = e>>5, c4 = (e&31)*4;
        float4 f = *(const float4*)&W[(size_t)(tk*32+r)*1536 + cb*128 + c4];
        sw[r][c4]=f.x; sw[r][c4+1]=f.y; sw[r][c4+2]=f.z; sw[r][c4+3]=f.w;
    }
    __syncthreads();
    uint4* dst = wp + (size_t)((z*12+cb)*48 + tk)*1024;
    #pragma unroll
    for (int i=0;i<4;i++){
        int slot = tid + i*256;
        int idx32 = slot>>5, lp = slot&31;
        int bs = idx32>>4, ntg = idx32&15;
        int base = lp ^ ((ntg&1)<<2);
        int gg = base>>2, bt = (base&3) ^ (gg>>1);
        int n = ntg*8 + gg;
        int k0 = bs*16 + 2*bt;
        uint4 w4;
        split_pair(sw[k0][n],   sw[k0+1][n], w4.x, w4.z);
        split_pair(sw[k0+8][n], sw[k0+9][n], w4.y, w4.w);
        dst[slot] = w4;
    }
}

// ---------------- two-phase stats (q and k fused via z) ----------------
__global__ void __launch_bounds__(256) stats_part(
    const float* __restrict__ q, const float* __restrict__ k,
    float* __restrict__ ps, float* __restrict__ pss)
{
    const int bh = blockIdx.x, part = blockIdx.y, z = blockIdx.z;
    const int tx = threadIdx.x & 63;
    const int ty = threadIdx.x >> 6;
    const float* p = (z ? k : q) + (size_t)bh * (z ? LK : LQ) * 64;
    float s = 0.f, ss = 0.f;
    for (int i = part*256 + ty; i < part*256 + 256; i += 4) {
        float v = p[(size_t)i*64 + tx];
        s += v; ss += v*v;
    }
    __shared__ float sh1[4][64], sh2[4][64];
    sh1[ty][tx] = s; sh2[ty][tx] = ss;
    __syncthreads();
    if (ty == 0) {
        int o = ((z*96+bh)*4+part)*64 + tx;
        ps [o] = sh1[0][tx]+sh1[1][tx]+sh1[2][tx]+sh1[3][tx];
        pss[o] = sh2[0][tx]+sh2[1][tx]+sh2[2][tx]+sh2[3][tx];
    }
}

__global__ void __launch_bounds__(64) stats_fin(
    const float* __restrict__ ps, const float* __restrict__ pss,
    float* __restrict__ mq, float* __restrict__ sq,
    float* __restrict__ mk, float* __restrict__ sk)
{
    const int bh = blockIdx.x, z = blockIdx.y, tx = threadIdx.x;
    float s = 0.f, ss = 0.f;
    #pragma unroll
    for (int p=0;p<4;p++){
        s  += ps [((z*96+bh)*4+p)*64 + tx];
        ss += pss[((z*96+bh)*4+p)*64 + tx];
    }
    float m = s * (1.0f/1024.0f);
    float var = (ss - 1024.0f*m*m) * (1.0f/1023.0f);
    (z ? mk : mq)[bh*64+tx] = m;
    (z ? sk : sq)[bh*64+tx] = sqrtf(var + 1e-5f);
}

// ---------------- AdaIN apply: q only (odd b) ----------------
__global__ void adain_q_kernel(
    float* __restrict__ q,
    const float* __restrict__ mq, const float* __restrict__ sq)
{
    const int idx = blockIdx.x * 256 + threadIdx.x;
    if (idx >= 2*24*1024*16) return;
    const int c  = (idx & 15) * 4;
    const int s  = (idx >> 4) & 1023;
    const int bhh = idx >> 14;
    const int bo = bhh / 24, h = bhh - bo*24;
    const int b  = 2*bo + 1;
    const int bh = b*24 + h;
    const int sbh = (b-1)*24 + h;

    const int ib = bh*64 + c, is = sbh*64 + c;
    float4 mb = *(const float4*)&mq[ib], sb = *(const float4*)&sq[ib];
    float4 ms = *(const float4*)&mq[is], so = *(const float4*)&sq[is];
    const size_t qi = ((size_t)bh*LQ + s)*64 + c;
    float4 x = *(const float4*)&q[qi];
    x.x = (x.x - mb.x)/sb.x*so.x + ms.x;
    x.y = (x.y - mb.y)/sb.y*so.y + ms.y;
    x.z = (x.z - mb.z)/sb.z*so.z + ms.z;
    x.w = (x.w - mb.w)/sb.w*so.w + ms.w;
    *(float4*)&q[qi] = x;
}

// ---------------- fused convert K (styling + remap) / V (remap) ----------
__global__ void __launch_bounds__(256) convert_k(
    const float* __restrict__ k,
    const float* __restrict__ mk, const float* __restrict__ sk,
    uint4* __restrict__ kf)
{
    const int kt = blockIdx.x, bh = blockIdx.y;
    const int b = bh / 24, h = bh - b*24;
    const bool odd = (b & 1);
    if (!odd && kt >= 16 && kt < 32) return;

    __shared__ float sK[64][65];
    __shared__ float pa[64], pc[64];
    const int tid = threadIdx.x;

    const float* src;
    bool style = false;
    if (kt < 16){ src = k + ((size_t)bh*LK + kt*64)*64; style = odd; }
    else if (kt < 32){ int sbh = (b-1)*24 + h; src = k + ((size_t)sbh*LK + (kt-16)*64)*64; }
    else { src = k + ((size_t)bh*LK + kt*64)*64; }

    if (style && tid < 64){
        int sbh = (b-1)*24 + h;
        float a = sk[sbh*64+tid] / sk[bh*64+tid];
        pa[tid] = a;
        pc[tid] = mk[sbh*64+tid] - mk[bh*64+tid]*a;
    }
    __syncthreads();
    #pragma unroll
    for (int i=0;i<16;i++){
        int e = tid + i*256;
        float x = src[e];
        if (style) x = fmaf(x, pa[e&63], pc[e&63]);
        sK[e>>6][e&63] = x;
    }
    __syncthreads();
    uint4* dst = kf + ((size_t)bh*36 + kt)*1024;
    #pragma unroll
    for (int i=0;i<4;i++){
        int slot = tid + i*256;
        int lane = slot & 31, nt = (slot>>5)&7, s = slot>>8;
        int g = lane>>2, t = lane&3;
        int kv = nt*8+g, d0 = 16*s+2*t;
        uint4 w4;
        split_pair(sK[kv][d0],   sK[kv][d0+1], w4.x, w4.z);
        split_pair(sK[kv][d0+8], sK[kv][d0+9], w4.y, w4.w);
        dst[slot] = w4;
    }
}

__global__ void __launch_bounds__(256) convert_v(
    const float* __restrict__ v, uint4* __restrict__ vf)
{
    const int kt = blockIdx.x, bh = blockIdx.y;
    const int b = bh / 24, h = bh - b*24;
    const bool odd = (b & 1);
    if (!odd && kt >= 16 && kt < 32) return;

    __shared__ float sV[64][65];
    const int tid = threadIdx.x;
    const float* src;
    if (kt < 32 && kt >= 16){ int sbh = (b-1)*24 + h; src = v + ((size_t)sbh*LK + (kt-16)*64)*64; }
    else { src = v + ((size_t)bh*LK + kt*64)*64; }

    #pragma unroll
    for (int i=0;i<16;i++){
        int e = tid + i*256;
        sV[e>>6][e&63] = src[e];
    }
    __syncthreads();
    uint4* dst = vf + ((size_t)bh*36 + kt)*1024;
    #pragma unroll
    for (int i=0;i<4;i++){
        int slot = tid + i*256;
        int lane = slot & 31, j = (slot>>5)&7, s2 = slot>>8;
        int g = lane>>2, t = lane&3;
        int d = j*8+g, r0 = 16*s2+2*t;
        uint4 w4;
        split_pair(sV[r0][d],   sV[r0+1][d], w4.x, w4.z);
        split_pair(sV[r0+8][d], sV[r0+9][d], w4.y, w4.w);
        dst[slot] = w4;
    }
}

// ================= split-bf16 flash attention, max-free softmax =============
// epilogue emits pre-split A rows for the output projection
#define AT_SMEM (2*2048*16)

__global__ void __launch_bounds__(256, 2) attn_bf3(
    const float* __restrict__ Q,
    const uint4* __restrict__ KF, const uint4* __restrict__ VF,
    uint32_t* __restrict__ AOH, uint32_t* __restrict__ AOL,
    uint32_t* __restrict__ EOH, uint32_t* __restrict__ EOL)
{
    extern __shared__ uint4 sm4[];
    const int tid = threadIdx.x, lane = tid & 31, w = tid >> 5;
    const int g = lane >> 2, t = lane & 3;
    const int qt = blockIdx.x, h = blockIdx.y, b = blockIdx.z;
    const bool odd = (b & 1);
    const int nkt = odd ? 36 : 20;
    const size_t bh = (size_t)b*NUM_H + h;
    const float* Qg = Q + (bh*LQ + (size_t)qt*128) * 64;
    const uint4* Kg = KF + bh*36*1024;
    const uint4* Vg = VF + bh*36*1024;
    const uint32_t smem_base = (uint32_t)__cvta_generic_to_shared(sm4);
    const float QSCALE = 0.125f * 1.44269504088896f;

#define KTOF(j_) ((odd || (j_) < 16) ? (j_) : (j_) + 16)
#define STAGE(kt_, buf_) { \
    uint32_t sb = smem_base + (buf_)*32768u; \
    const uint4* kp = Kg + (size_t)(kt_)*1024 + tid; \
    const uint4* vp = Vg + (size_t)(kt_)*1024 + tid; \
    _Pragma("unroll") \
    for (int i_=0;i_<4;i_++){ \
        cp16(sb + (uint32_t)(tid + i_*256)*16u,           kp + i_*256); \
        cp16(sb + 16384u + (uint32_t)(tid + i_*256)*16u,  vp + i_*256); \
    } \
    asm volatile("cp.async.commit_group;"); }

    STAGE(0, 0);

    uint32_t qh[4][4], ql[4][4];
    {
        const int r0 = w*16 + g;
        #pragma unroll
        for (int s=0;s<4;s++){
            int d0 = 16*s + 2*t;
            float2 x00 = *(const float2*)&Qg[(size_t)r0*64 + d0];
            float2 x10 = *(const float2*)&Qg[(size_t)(r0+8)*64 + d0];
            float2 x01 = *(const float2*)&Qg[(size_t)r0*64 + d0 + 8];
            float2 x11 = *(const float2*)&Qg[(size_t)(r0+8)*64 + d0 + 8];
            split_pair(x00.x*QSCALE, x00.y*QSCALE, qh[s][0], ql[s][0]);
            split_pair(x10.x*QSCALE, x10.y*QSCALE, qh[s][1], ql[s][1]);
            split_pair(x01.x*QSCALE, x01.y*QSCALE, qh[s][2], ql[s][2]);
            split_pair(x11.x*QSCALE, x11.y*QSCALE, qh[s][3], ql[s][3]);
        }
    }

    float o_[8][4];
    #pragma unroll
    for (int j=0;j<8;j++){ o_[j][0]=0.f; o_[j][1]=0.f; o_[j][2]=0.f; o_[j][3]=0.f; }
    float l0s=0.f, l1s=0.f;

    for (int jj=0; jj<nkt; jj++){
        asm volatile("cp.async.wait_group 0;");
        __syncthreads();
        if (jj+1 < nkt) { STAGE(KTOF(jj+1), (jj+1)&1); }

        const uint4* Kt = sm4 + (jj&1)*2048;
        const uint4* Vt = Kt + 1024;
        const float padd = (!odd && jj < 16) ? 1.0f : 0.0f;

        float s_[8][4];
        #pragma unroll
        for (int j=0;j<8;j++){ s_[j][0]=0.f; s_[j][1]=0.f; s_[j][2]=0.f; s_[j][3]=0.f; }
        #pragma unroll
        for (int s=0;s<4;s++)
            #pragma unroll
            for (int nt=0;nt<8;nt++){
                uint4 kw = Kt[(s*8+nt)*32 + lane];
                mma16(s_[nt], qh[s], kw.x, kw.y);
                mma16(s_[nt], qh[s], kw.z, kw.w);
                mma16(s_[nt], ql[s], kw.x, kw.y);
            }

        #pragma unroll
        for (int j=0;j<8;j++){
            s_[j][0]=exp2f(s_[j][0]+padd); s_[j][1]=exp2f(s_[j][1]+padd);
            s_[j][2]=exp2f(s_[j][2]+padd); s_[j][3]=exp2f(s_[j][3]+padd);
            l0s += s_[j][0]+s_[j][1];
            l1s += s_[j][2]+s_[j][3];
        }

        uint32_t ph[4][4], pl[4][4];
        #pragma unroll
        for (int s2=0;s2<4;s2++){
            split_pair(s_[2*s2][0],   s_[2*s2][1],   ph[s2][0], pl[s2][0]);
            split_pair(s_[2*s2][2],   s_[2*s2][3],   ph[s2][1], pl[s2][1]);
            split_pair(s_[2*s2+1][0], s_[2*s2+1][1], ph[s2][2], pl[s2][2]);
            split_pair(s_[2*s2+1][2], s_[2*s2+1][3], ph[s2][3], pl[s2][3]);
        }

        #pragma unroll
        for (int s2=0;s2<4;s2++)
            #pragma unroll
            for (int j=0;j<8;j++){
                uint4 vw = Vt[(s2*8+j)*32 + lane];
                mma16(o_[j], ph[s2], vw.x, vw.y);
                mma16(o_[j], ph[s2], vw.z, vw.w);
                mma16(o_[j], pl[s2], vw.x, vw.y);
            }
    }
#undef STAGE
#undef KTOF

    l0s += __shfl_xor_sync(0xffffffffu, l0s, 1);
    l0s += __shfl_xor_sync(0xffffffffu, l0s, 2);
    l1s += __shfl_xor_sync(0xffffffffu, l1s, 1);
    l1s += __shfl_xor_sync(0xffffffffu, l1s, 2);
    float inv0 = 1.0f / l0s, inv1 = 1.0f / l1s;
    int q0 = qt*128 + w*16 + g;

    uint32_t *OH, *OL;
    size_t rbase;
    if (q0 < 1024){ OH = AOH; OL = AOL; rbase = (size_t)(b*1024 + q0)*768; }
    else          { OH = EOH; OL = EOL; rbase = (size_t)(b*256 + q0 - 1024)*768; }
    #pragma unroll
    for (int j=0;j<8;j++){
        int cw = h*32 + j*4 + t;
        uint32_t hh, ll;
        split_pair(o_[j][0]*inv0, o_[j][1]*inv0, hh, ll);
        OH[rbase + cw] = hh; OL[rbase + cw] = ll;
        split_pair(o_[j][2]*inv1, o_[j][3]*inv1, hh, ll);
        OH[rbase + 8*768 + cw] = hh; OL[rbase + 8*768 + cw] = ll;
    }
}

// ---------------- launch ----------------
extern "C" void kernel_launch(void* const* d_in, const int* in_sizes, int n_in,
                              void* d_out, int out_size)
{
    (void)in_sizes; (void)n_in; (void)out_size;
    const float* hs  = (const float*)d_in[0];
    const float* ehs = (const float*)d_in[1];
    const float* wq  = (const float*)d_in[2];  const float* bq  = (const float*)d_in[3];
    const float* wk  = (const float*)d_in[4];  const float* bk  = (const float*)d_in[5];
    const float* wv  = (const float*)d_in[6];  const float* bv  = (const float*)d_in[7];
    const float* awq = (const float*)d_in[8];  const float* abq = (const float*)d_in[9];
    const float* awk = (const float*)d_in[10]; const float* abk = (const float*)d_in[11];
    const float* awv = (const float*)d_in[12]; const float* abv = (const float*)d_in[13];
    const float* wo  = (const float*)d_in[14]; const float* bo  = (const float*)d_in[15];
    const float* wao = (const float*)d_in[16]; const float* bao = (const float*)d_in[17];
    float* out = (float*)d_out;

    float *q, *k, *v, *mq, *sq, *mk, *sk, *ps, *pss;
    uint4 *kf, *vf, *wp;
    uint32_t *hsh, *hsl, *esh, *esl, *aoh, *aol, *eoh, *eol;
    cudaGetSymbolAddress((void**)&q,  g_q);
    cudaGetSymbolAddress((void**)&k,  g_k);
    cudaGetSymbolAddress((void**)&v,  g_v);
    cudaGetSymbolAddress((void**)&mq, g_mq);
    cudaGetSymbolAddress((void**)&sq, g_sq);
    cudaGetSymbolAddress((void**)&mk, g_mk);
    cudaGetSymbolAddress((void**)&sk, g_sk);
    cudaGetSymbolAddress((void**)&ps, g_ps);
    cudaGetSymbolAddress((void**)&pss, g_pss);
    cudaGetSymbolAddress((void**)&kf, g_kf);
    cudaGetSymbolAddress((void**)&vf, g_vf);
    cudaGetSymbolAddress((void**)&wp, g_wp);
    cudaGetSymbolAddress((void**)&hsh, g_hsh);
    cudaGetSymbolAddress((void**)&hsl, g_hsl);
    cudaGetSymbolAddress((void**)&esh, g_esh);
    cudaGetSymbolAddress((void**)&esl, g_esl);
    cudaGetSymbolAddress((void**)&aoh, g_aoh);
    cudaGetSymbolAddress((void**)&aol, g_aol);
    cudaGetSymbolAddress((void**)&eoh, g_eoh);
    cudaGetSymbolAddress((void**)&eol, g_eol);

    static int attr_set = 0;
    if (!attr_set) {
        cudaFuncSetAttribute(gemm_qkv, cudaFuncAttributeMaxDynamicSharedMemorySize, GEMM_SMEM);
        cudaFuncSetAttribute(gemm_out, cudaFuncAttributeMaxDynamicSharedMemorySize, GEMM_SMEM);
        cudaFuncSetAttribute(attn_bf3, cudaFuncAttributeMaxDynamicSharedMemorySize, AT_SMEM);
        attr_set = 1;
    }

    // operand pre-conversion
    conv_a<<<6144, 256>>>(hs,  hsh, hsl, 4096*384);
    conv_a<<<1536, 256>>>(ehs, esh, esl, 1024*384);
    conv_wp<<<dim3(12, 48, 8), 256>>>(wq, wk, wv, awq, awk, awv, wo, wao, wp);

    // QKV projections
    gemm_qkv<<<dim3(12, 32, 3), 512, GEMM_SMEM>>>(
        hsh, hsl, wp, 0, bq, bk, bv, q, k, v,
        1024, LQ, LK, LK, 0, 0, 0);
    gemm_qkv<<<dim3(12, 8, 3), 512, GEMM_SMEM>>>(
        esh, esl, wp, 3, abq, abk, abv, q, k, v,
        256, LQ, LK, LK, 1024, 2048, 2048);

    // stats (q,k fused)
    stats_part<<<dim3(96, 4, 2), 256>>>(q, k, ps, pss);
    stats_fin<<<dim3(96, 2), 64>>>(ps, pss, mq, sq, mk, sk);

    adain_q_kernel<<<3072, 256>>>(q, mq, sq);
    convert_k<<<dim3(36, 96), 256>>>(k, mk, sk, kf);
    convert_v<<<dim3(36, 96), 256>>>(v, vf);

    attn_bf3<<<dim3(10, 24, 4), 256, AT_SMEM>>>(q, kf, vf, aoh, aol, eoh, eol);

    // output projections
    gemm_out<<<dim3(12, 32, 2), 512, GEMM_SMEM>>>(
        aoh, aol, eoh, eol, wp, 6, bo, bao,
        out, out + (size_t)4096*1536);
}

// round 14
// speedup vs baseline: 1.3311x; 1.0309x over previous
#include <cuda_runtime.h>
#include <cuda_bf16.h>
#include <math.h>
#include <stdint.h>

#define NUM_H 24
#define LQ 1280
#define LK 2304

// ---------------- scratch (device globals; no allocations) ----------------
__device__ float g_q[4*24*1280*64];      // (B,H,LQ,64)
__device__ float g_k[4*24*2304*64];
__device__ float g_v[4*24*2304*64];
__device__ float g_mq[6144], g_sq[6144], g_mk[6144], g_sk[6144];
__device__ float g_ps[2*96*4*64], g_pss[2*96*4*64];   // stats partials (q,k)
// fragment-packed K/V for attention (tiles 16..31 never materialized)
__device__ uint4 g_kf[96*36*1024];
__device__ uint4 g_vf[96*36*1024];
// pre-split GEMM operands (u32 = bf16x2 over k-pairs)
__device__ uint32_t g_hsh[4096*768], g_hsl[4096*768];
__device__ uint32_t g_esh[1024*768], g_esl[1024*768];
__device__ uint32_t g_aoh[4096*768], g_aol[4096*768];
__device__ uint32_t g_eoh[1024*768], g_eol[1024*768];
// weights packed in B-fragment slot layout: [z][colblk 12][tk 48][1024 uint4]
__device__ uint4 g_wp[8*12*48*1024];

// ---------------- bf16 helpers ----------------
__device__ __forceinline__ void split_pair(float x, float y, uint32_t &hi, uint32_t &lo){
    __nv_bfloat162 hv = __floats2bfloat162_rn(x, y);
    hi = *reinterpret_cast<uint32_t*>(&hv);
    float rx = x - __low2float(hv);
    float ry = y - __high2float(hv);
    __nv_bfloat162 lv = __floats2bfloat162_rn(rx, ry);
    lo = *reinterpret_cast<uint32_t*>(&lv);
}

__device__ __forceinline__ void mma16(float* c, const uint32_t* a, uint32_t b0, uint32_t b1){
    asm volatile("mma.sync.aligned.m16n8k16.row.col.f32.bf16.bf16.f32 "
        "{%0,%1,%2,%3},{%4,%5,%6,%7},{%8,%9},{%0,%1,%2,%3};"
        : "+f"(c[0]),"+f"(c[1]),"+f"(c[2]),"+f"(c[3])
        : "r"(a[0]),"r"(a[1]),"r"(a[2]),"r"(a[3]),"r"(b0),"r"(b1));
}

__device__ __forceinline__ void ldsm4(uint32_t* r, uint32_t addr){
    asm volatile("ldmatrix.sync.aligned.m8n8.x4.shared.b16 {%0,%1,%2,%3}, [%4];"
        : "=r"(r[0]),"=r"(r[1]),"=r"(r[2]),"=r"(r[3]) : "r"(addr));
}

__device__ __forceinline__ void cp16(uint32_t saddr, const void* gptr){
    asm volatile("cp.async.cg.shared.global [%0], [%1], 16;" :: "r"(saddr), "l"(gptr));
}

// ===== split-bf16 GEMM: 128x256 tile, BK=32, 1024 threads, 3-stage =========
// 32 warps as 4m x 8n (8n spans two 128-col weight blocks), warp tile 32x32.
// Stage (48KB): Ah[8KB] Al[8KB] B0[16KB] B1[16KB].
#define GSTG 49152u
#define GEMM_SMEM (3*49152)    // 147456 B

__device__ __forceinline__ void gemm_core(
    const uint32_t* __restrict__ Ah, const uint32_t* __restrict__ Al,  // [M][768]
    const uint4* __restrict__ Bp0, const uint4* __restrict__ Bp1,      // [48][1024] each
    const float* __restrict__ bias, float* __restrict__ out,
    int heads_mode, int S_rows, int L, int s_off,
    int row0, int colblk0, uint32_t* sm)
{
    const int tid = threadIdx.x, lane = tid & 31, wrp = tid >> 5;
    const int g = lane >> 2, t = lane & 3;
    const int wm = wrp >> 3;              // 0..3
    const int wnl = wrp & 7;              // 0..7
    const int j = wnl >> 2;               // col-block within tile
    const int wn4 = wnl & 3;              // 32-col slice within block

    float acc[2][4][4];
    #pragma unroll
    for (int i=0;i<2;i++)
        #pragma unroll
        for (int jj=0;jj<4;jj++)
            #pragma unroll
            for (int r=0;r<4;r++) acc[i][jj][r]=0.f;

    const uint32_t sbase = (uint32_t)__cvta_generic_to_shared(sm);
    uint32_t a_off[2][2];
    #pragma unroll
    for (int mt=0; mt<2; mt++){
        int r = wm*32 + mt*16 + ((lane>>3)&1)*8 + (lane&7);
        int swz = (r>>1)&3;
        #pragma unroll
        for (int s=0; s<2; s++){
            int u = s*2 + (lane>>4);
            a_off[mt][s] = (uint32_t)(r*64 + ((u ^ swz)<<4));
        }
    }
    uint32_t b_slot[2][4];
    #pragma unroll
    for (int s=0; s<2; s++)
        #pragma unroll
        for (int nt=0; nt<4; nt++){
            int ntg = wn4*4 + nt;
            int lp = ((g*4+t) ^ (g>>1)) ^ ((ntg&1)<<2);
            b_slot[s][nt] = (uint32_t)(j*1024 + (s*16+ntg)*32 + lp);
        }

    // staging maps: 1024 threads do 1 A-cp16 + 2 B-cp16 each
    const uint32_t aunit = (uint32_t)(tid & 511);
    const uint32_t ar = aunit >> 2, au = aunit & 3;
    const uint32_t a_so = (tid < 512 ? 0u : 8192u) + ar*64 + ((au ^ ((ar>>1)&3))<<4);
    const uint32_t* Asrc = (tid < 512) ? Ah : Al;

#define STAGE(tk_, st_) { \
    uint32_t sb = sbase + (uint32_t)(st_)*GSTG; \
    cp16(sb + a_so, Asrc + (size_t)(row0+ar)*768 + (uint32_t)(tk_)*16u + au*4); \
    cp16(sb + 16384u + (uint32_t)tid*16u, Bp0 + (size_t)(tk_)*1024 + tid); \
    cp16(sb + 32768u + (uint32_t)tid*16u, Bp1 + (size_t)(tk_)*1024 + tid); \
    asm volatile("cp.async.commit_group;" ::: "memory"); }

    STAGE(0, 0);
    STAGE(1, 1);

    const int nT = 48;
    for (int tk=0; tk<nT; tk++){
        const int st = tk % 3;
        if (tk+1 < nT) asm volatile("cp.async.wait_group 1;" ::: "memory");
        else           asm volatile("cp.async.wait_group 0;" ::: "memory");
        __syncthreads();
        const uint32_t bufb = sbase + (uint32_t)st*GSTG;
        const uint4* Bs = (const uint4*)(sm + st*12288 + 4096);
        #pragma unroll
        for (int s=0;s<2;s++){
            uint32_t ah[2][4], al[2][4];
            #pragma unroll
            for (int mt=0;mt<2;mt++){
                ldsm4(ah[mt], bufb + a_off[mt][s]);
                ldsm4(al[mt], bufb + 8192u + a_off[mt][s]);
            }
            #pragma unroll
            for (int nt=0;nt<4;nt++){
                uint4 kw = Bs[b_slot[s][nt]];
                #pragma unroll
                for (int mt=0;mt<2;mt++){
                    mma16(acc[mt][nt], ah[mt], kw.x, kw.y);
                    mma16(acc[mt][nt], ah[mt], kw.z, kw.w);
                    mma16(acc[mt][nt], al[mt], kw.x, kw.y);
                }
            }
        }
        if (tk+2 < nT) { STAGE(tk+2, (tk+2)%3); }
    }
#undef STAGE

    #pragma unroll
    for (int mt=0;mt<2;mt++){
        int m0r = row0 + wm*32 + mt*16 + g;
        #pragma unroll
        for (int nt=0;nt<4;nt++){
            int c = (colblk0 + j)*128 + wn4*32 + nt*8 + t*2;
            float b0v = bias[c], b1v = bias[c+1];
            float2 v0 = make_float2(acc[mt][nt][0]+b0v, acc[mt][nt][1]+b1v);
            float2 v1 = make_float2(acc[mt][nt][2]+b0v, acc[mt][nt][3]+b1v);
            if (!heads_mode){
                *(float2*)&out[(size_t)m0r*1536 + c]     = v0;
                *(float2*)&out[(size_t)(m0r+8)*1536 + c] = v1;
            } else {
                int hh = c >> 6, hd = c & 63;
                int bb = m0r / S_rows, ss = m0r - bb*S_rows;
                *(float2*)&out[((size_t)(bb*NUM_H+hh)*L + s_off + ss)*64 + hd] = v0;
                int m1r = m0r + 8;
                int bb1 = m1r / S_rows, ss1 = m1r - bb1*S_rows;
                *(float2*)&out[((size_t)(bb1*NUM_H+hh)*L + s_off + ss1)*64 + hd] = v1;
            }
        }
    }
}

__global__ void __launch_bounds__(1024, 1) gemm_qkv(
    const uint32_t* __restrict__ Ah, const uint32_t* __restrict__ Al,
    const uint4* __restrict__ WP, int widx0,
    const float* __restrict__ b0, const float* __restrict__ b1, const float* __restrict__ b2,
    float* __restrict__ o0, float* __restrict__ o1, float* __restrict__ o2,
    int S_rows, int L0, int L1, int L2, int soff0, int soff1, int soff2)
{
    extern __shared__ uint32_t sm[];
    const int z = blockIdx.z;
    const float* bi = (z==0)? b0 : (z==1)? b1 : b2;
    float* out = (z==0)? o0 : (z==1)? o1 : o2;
    int L = (z==0)? L0 : (z==1)? L1 : L2;
    int soff = (z==0)? soff0 : (z==1)? soff1 : soff2;
    const uint4* Bp0 = WP + (size_t)((widx0+z)*12 + blockIdx.x*2)*48*1024;
    gemm_core(Ah, Al, Bp0, Bp0 + 48*1024, bi, out, 1, S_rows, L, soff,
              blockIdx.y*128, blockIdx.x*2, sm);
}

__global__ void __launch_bounds__(1024, 1) gemm_out(
    const uint32_t* __restrict__ A0h, const uint32_t* __restrict__ A0l,
    const uint32_t* __restrict__ A1h, const uint32_t* __restrict__ A1l,
    const uint4* __restrict__ WP, int widx0,
    const float* __restrict__ b0, const float* __restrict__ b1,
    float* __restrict__ o0, float* __restrict__ o1)
{
    extern __shared__ uint32_t sm[];
    const int z = blockIdx.z;
    if (z == 1 && blockIdx.y >= 8) return;
    const uint4* Bp0 = WP + (size_t)((widx0+z)*12 + blockIdx.x*2)*48*1024;
    gemm_core((z==0)? A0h : A1h, (z==0)? A0l : A1l, Bp0, Bp0 + 48*1024,
              (z==0)? b0 : b1, (z==0)? o0 : o1,
              0, 0, 0, 0, blockIdx.y*128, blockIdx.x*2, sm);
}

// ---------------- operand pre-conversion ----------------
__global__ void __launch_bounds__(256) conv_a(
    const float* __restrict__ x, uint32_t* __restrict__ hi, uint32_t* __restrict__ lo, int n4)
{
    int i = blockIdx.x*256 + threadIdx.x;
    if (i >= n4) return;
    float4 f = ((const float4*)x)[i];
    uint2 h, l;
    split_pair(f.x, f.y, h.x, l.x);
    split_pair(f.z, f.w, h.y, l.y);
    ((uint2*)hi)[i] = h; ((uint2*)lo)[i] = l;
}

__global__ void __launch_bounds__(256) conv_wp(
    const float* w0, const float* w1, const float* w2, const float* w3,
    const float* w4, const float* w5, const float* w6, const float* w7,
    uint4* __restrict__ wp)
{
    __shared__ float sw[32][129];
    const int cb = blockIdx.x, tk = blockIdx.y, z = blockIdx.z;
    const float* W = (z==0)?w0:(z==1)?w1:(z==2)?w2:(z==3)?w3:(z==4)?w4:(z==5)?w5:(z==6)?w6:w7;
    const int tid = threadIdx.x;
    #pragma unroll
    for (int i=0;i<4;i++){
        int e = tid + i*256;
        int r = e>>5, c4 = (e&31)*4;
        float4 f = *(const float4*)&W[(size_t)(tk*32+r)*1536 + cb*128 + c4];
        sw[r][c4]=f.x; sw[r][c4+1]=f.y; sw[r][c4+2]=f.z; sw[r][c4+3]=f.w;
    }
    __syncthreads();
    uint4* dst = wp + (size_t)((z*12+cb)*48 + tk)*1024;
    #pragma unroll
    for (int i=0;i<4;i++){
        int slot = tid + i*256;
        int idx32 = slot>>5, lp = slot&31;
        int bs = idx32>>4, ntg = idx32&15;
        int base = lp ^ ((ntg&1)<<2);
        int gg = base>>2, bt = (base&3) ^ (gg>>1);
        int n = ntg*8 + gg;
        int k0 = bs*16 + 2*bt;
        uint4 w4;
        split_pair(sw[k0][n],   sw[k0+1][n], w4.x, w4.z);
        split_pair(sw[k0+8][n], sw[k0+9][n], w4.y, w4.w);
        dst[slot] = w4;
    }
}

// ---------------- two-phase stats (q and k fused via z) ----------------
__global__ void __launch_bounds__(256) stats_part(
    const float* __restrict__ q, const float* __restrict__ k,
    float* __restrict__ ps, float* __restrict__ pss)
{
    const int bh = blockIdx.x, part = blockIdx.y, z = blockIdx.z;
    const int tx = threadIdx.x & 63;
    const int ty = threadIdx.x >> 6;
    const float* p = (z ? k : q) + (size_t)bh * (z ? LK : LQ) * 64;
    float s = 0.f, ss = 0.f;
    for (int i = part*256 + ty; i < part*256 + 256; i += 4) {
        float v = p[(size_t)i*64 + tx];
        s += v; ss += v*v;
    }
    __shared__ float sh1[4][64], sh2[4][64];
    sh1[ty][tx] = s; sh2[ty][tx] = ss;
    __syncthreads();
    if (ty == 0) {
        int o = ((z*96+bh)*4+part)*64 + tx;
        ps [o] = sh1[0][tx]+sh1[1][tx]+sh1[2][tx]+sh1[3][tx];
        pss[o] = sh2[0][tx]+sh2[1][tx]+sh2[2][tx]+sh2[3][tx];
    }
}

__global__ void __launch_bounds__(64) stats_fin(
    const float* __restrict__ ps, const float* __restrict__ pss,
    float* __restrict__ mq, float* __restrict__ sq,
    float* __restrict__ mk, float* __restrict__ sk)
{
    const int bh = blockIdx.x, z = blockIdx.y, tx = threadIdx.x;
    float s = 0.f, ss = 0.f;
    #pragma unroll
    for (int p=0;p<4;p++){
        s  += ps [((z*96+bh)*4+p)*64 + tx];
        ss += pss[((z*96+bh)*4+p)*64 + tx];
    }
    float m = s * (1.0f/1024.0f);
    float var = (ss - 1024.0f*m*m) * (1.0f/1023.0f);
    (z ? mk : mq)[bh*64+tx] = m;
    (z ? sk : sq)[bh*64+tx] = sqrtf(var + 1e-5f);
}

// ---------------- AdaIN apply: q only (odd b) ----------------
__global__ void adain_q_kernel(
    float* __restrict__ q,
    const float* __restrict__ mq, const float* __restrict__ sq)
{
    const int idx = blockIdx.x * 256 + threadIdx.x;
    if (idx >= 2*24*1024*16) return;
    const int c  = (idx & 15) * 4;
    const int s  = (idx >> 4) & 1023;
    const int bhh = idx >> 14;
    const int bo = bhh / 24, h = bhh - bo*24;
    const int b  = 2*bo + 1;
    const int bh = b*24 + h;
    const int sbh = (b-1)*24 + h;

    const int ib = bh*64 + c, is = sbh*64 + c;
    float4 mb = *(const float4*)&mq[ib], sb = *(const float4*)&sq[ib];
    float4 ms = *(const float4*)&mq[is], so = *(const float4*)&sq[is];
    const size_t qi = ((size_t)bh*LQ + s)*64 + c;
    float4 x = *(const float4*)&q[qi];
    x.x = (x.x - mb.x)/sb.x*so.x + ms.x;
    x.y = (x.y - mb.y)/sb.y*so.y + ms.y;
    x.z = (x.z - mb.z)/sb.z*so.z + ms.z;
    x.w = (x.w - mb.w)/sb.w*so.w + ms.w;
    *(float4*)&q[qi] = x;
}

// ---------------- convert K (styling) / V: tiles {0..15, 32..35} only ------
__global__ void __launch_bounds__(256) convert_k(
    const float* __restrict__ k,
    const float* __restrict__ mk, const float* __restrict__ sk,
    uint4* __restrict__ kf)
{
    const int x = blockIdx.x, bh = blockIdx.y;
    const int kt = (x < 16) ? x : x + 16;
    const int b = bh / 24, h = bh - b*24;
    const bool style = (b & 1) && (kt < 16);

    __shared__ float sK[64][65];
    __shared__ float pa[64], pc[64];
    const int tid = threadIdx.x;
    const float* src = k + ((size_t)bh*LK + kt*64)*64;

    if (style && tid < 64){
        int sbh = (b-1)*24 + h;
        float a = sk[sbh*64+tid] / sk[bh*64+tid];
        pa[tid] = a;
        pc[tid] = mk[sbh*64+tid] - mk[bh*64+tid]*a;
    }
    __syncthreads();
    #pragma unroll
    for (int i=0;i<16;i++){
        int e = tid + i*256;
        float xv = src[e];
        if (style) xv = fmaf(xv, pa[e&63], pc[e&63]);
        sK[e>>6][e&63] = xv;
    }
    __syncthreads();
    uint4* dst = kf + ((size_t)bh*36 + kt)*1024;
    #pragma unroll
    for (int i=0;i<4;i++){
        int slot = tid + i*256;
        int lane = slot & 31, nt = (slot>>5)&7, s = slot>>8;
        int g = lane>>2, t = lane&3;
        int kv = nt*8+g, d0 = 16*s+2*t;
        uint4 w4;
        split_pair(sK[kv][d0],   sK[kv][d0+1], w4.x, w4.z);
        split_pair(sK[kv][d0+8], sK[kv][d0+9], w4.y, w4.w);
        dst[slot] = w4;
    }
}

__global__ void __launch_bounds__(256) convert_v(
    const float* __restrict__ v, uint4* __restrict__ vf)
{
    const int x = blockIdx.x, bh = blockIdx.y;
    const int kt = (x < 16) ? x : x + 16;

    __shared__ float sV[64][65];
    const int tid = threadIdx.x;
    const float* src = v + ((size_t)bh*LK + kt*64)*64;

    #pragma unroll
    for (int i=0;i<16;i++){
        int e = tid + i*256;
        sV[e>>6][e&63] = src[e];
    }
    __syncthreads();
    uint4* dst = vf + ((size_t)bh*36 + kt)*1024;
    #pragma unroll
    for (int i=0;i<4;i++){
        int slot = tid + i*256;
        int lane = slot & 31, j = (slot>>5)&7, s2 = slot>>8;
        int g = lane>>2, t = lane&3;
        int d = j*8+g, r0 = 16*s2+2*t;
        uint4 w4;
        split_pair(sV[r0][d],   sV[r0+1][d], w4.x, w4.z);
        split_pair(sV[r0+8][d], sV[r0+9][d], w4.y, w4.w);
        dst[slot] = w4;
    }
}

// ================= split-bf16 flash attention, max-free softmax =============
// odd b: tiles 16..31 read from the (unstyled) source batch's tiles 0..15.
// even b: tiles 0..15 weighted x2 via exp2(s+1); then encoder tiles 32..35.
#define AT_SMEM (2*2048*16)

__global__ void __launch_bounds__(256, 2) attn_bf3(
    const float* __restrict__ Q,
    const uint4* __restrict__ KF, const uint4* __restrict__ VF,
    uint32_t* __restrict__ AOH, uint32_t* __restrict__ AOL,
    uint32_t* __restrict__ EOH, uint32_t* __restrict__ EOL)
{
    extern __shared__ uint4 sm4[];
    const int tid = threadIdx.x, lane = tid & 31, w = tid >> 5;
    const int g = lane >> 2, t = lane & 3;
    const int qt = blockIdx.x, h = blockIdx.y, b = blockIdx.z;
    const bool odd = (b & 1);
    const int nkt = odd ? 36 : 20;
    const size_t bh = (size_t)b*NUM_H + h;
    const float* Qg = Q + (bh*LQ + (size_t)qt*128) * 64;
    const uint4* Kg = KF + bh*36*1024;
    const uint4* Vg = VF + bh*36*1024;
    const uint4* KgS = Kg - (size_t)24*36*1024;   // source batch (b-1), valid when odd
    const uint4* VgS = Vg - (size_t)24*36*1024;
    const uint32_t smem_base = (uint32_t)__cvta_generic_to_shared(sm4);
    const float QSCALE = 0.125f * 1.44269504088896f;

#define STAGE(jj_, buf_) { \
    int kt_; const uint4 *kb_, *vb_; \
    if (odd){ \
        if ((jj_) >= 16 && (jj_) < 32){ kt_ = (jj_) - 16; kb_ = KgS; vb_ = VgS; } \
        else { kt_ = (jj_); kb_ = Kg; vb_ = Vg; } \
    } else { \
        kt_ = ((jj_) < 16) ? (jj_) : (jj_) + 16; kb_ = Kg; vb_ = Vg; \
    } \
    uint32_t sb = smem_base + (buf_)*32768u; \
    const uint4* kp = kb_ + (size_t)kt_*1024 + tid; \
    const uint4* vp = vb_ + (size_t)kt_*1024 + tid; \
    _Pragma("unroll") \
    for (int i_=0;i_<4;i_++){ \
        cp16(sb + (uint32_t)(tid + i_*256)*16u,           kp + i_*256); \
        cp16(sb + 16384u + (uint32_t)(tid + i_*256)*16u,  vp + i_*256); \
    } \
    asm volatile("cp.async.commit_group;"); }

    STAGE(0, 0);

    uint32_t qh[4][4], ql[4][4];
    {
        const int r0 = w*16 + g;
        #pragma unroll
        for (int s=0;s<4;s++){
            int d0 = 16*s + 2*t;
            float2 x00 = *(const float2*)&Qg[(size_t)r0*64 + d0];
            float2 x10 = *(const float2*)&Qg[(size_t)(r0+8)*64 + d0];
            float2 x01 = *(const float2*)&Qg[(size_t)r0*64 + d0 + 8];
            float2 x11 = *(const float2*)&Qg[(size_t)(r0+8)*64 + d0 + 8];
            split_pair(x00.x*QSCALE, x00.y*QSCALE, qh[s][0], ql[s][0]);
            split_pair(x10.x*QSCALE, x10.y*QSCALE, qh[s][1], ql[s][1]);
            split_pair(x01.x*QSCALE, x01.y*QSCALE, qh[s][2], ql[s][2]);
            split_pair(x11.x*QSCALE, x11.y*QSCALE, qh[s][3], ql[s][3]);
        }
    }

    float o_[8][4];
    #pragma unroll
    for (int jq=0;jq<8;jq++){ o_[jq][0]=0.f; o_[jq][1]=0.f; o_[jq][2]=0.f; o_[jq][3]=0.f; }
    float l0s=0.f, l1s=0.f;

    for (int jj=0; jj<nkt; jj++){
        asm volatile("cp.async.wait_group 0;");
        __syncthreads();
        if (jj+1 < nkt) { STAGE(jj+1, (jj+1)&1); }

        const uint4* Kt = sm4 + (jj&1)*2048;
        const uint4* Vt = Kt + 1024;
        const float padd = (!odd && jj < 16) ? 1.0f : 0.0f;

        float s_[8][4];
        #pragma unroll
        for (int jq=0;jq<8;jq++){ s_[jq][0]=0.f; s_[jq][1]=0.f; s_[jq][2]=0.f; s_[jq][3]=0.f; }
        #pragma unroll
        for (int s=0;s<4;s++)
            #pragma unroll
            for (int nt=0;nt<8;nt++){
                uint4 kw = Kt[(s*8+nt)*32 + lane];
                mma16(s_[nt], qh[s], kw.x, kw.y);
                mma16(s_[nt], qh[s], kw.z, kw.w);
                mma16(s_[nt], ql[s], kw.x, kw.y);
            }

        #pragma unroll
        for (int jq=0;jq<8;jq++){
            s_[jq][0]=exp2f(s_[jq][0]+padd); s_[jq][1]=exp2f(s_[jq][1]+padd);
            s_[jq][2]=exp2f(s_[jq][2]+padd); s_[jq][3]=exp2f(s_[jq][3]+padd);
            l0s += s_[jq][0]+s_[jq][1];
            l1s += s_[jq][2]+s_[jq][3];
        }

        uint32_t ph[4][4], pl[4][4];
        #pragma unroll
        for (int s2=0;s2<4;s2++){
            split_pair(s_[2*s2][0],   s_[2*s2][1],   ph[s2][0], pl[s2][0]);
            split_pair(s_[2*s2][2],   s_[2*s2][3],   ph[s2][1], pl[s2][1]);
            split_pair(s_[2*s2+1][0], s_[2*s2+1][1], ph[s2][2], pl[s2][2]);
            split_pair(s_[2*s2+1][2], s_[2*s2+1][3], ph[s2][3], pl[s2][3]);
        }

        #pragma unroll
        for (int s2=0;s2<4;s2++)
            #pragma unroll
            for (int jq=0;jq<8;jq++){
                uint4 vw = Vt[(s2*8+jq)*32 + lane];
                mma16(o_[jq], ph[s2], vw.x, vw.y);
                mma16(o_[jq], ph[s2], vw.z, vw.w);
                mma16(o_[jq], pl[s2], vw.x, vw.y);
            }
    }
#undef STAGE

    l0s += __shfl_xor_sync(0xffffffffu, l0s, 1);
    l0s += __shfl_xor_sync(0xffffffffu, l0s, 2);
    l1s += __shfl_xor_sync(0xffffffffu, l1s, 1);
    l1s += __shfl_xor_sync(0xffffffffu, l1s, 2);
    float inv0 = 1.0f / l0s, inv1 = 1.0f / l1s;
    int q0 = qt*128 + w*16 + g;

    uint32_t *OH, *OL;
    size_t rbase;
    if (q0 < 1024){ OH = AOH; OL = AOL; rbase = (size_t)(b*1024 + q0)*768; }
    else          { OH = EOH; OL = EOL; rbase = (size_t)(b*256 + q0 - 1024)*768; }
    #pragma unroll
    for (int jq=0;jq<8;jq++){
        int cw = h*32 + jq*4 + t;
        uint32_t hh, ll;
        split_pair(o_[jq][0]*inv0, o_[jq][1]*inv0, hh, ll);
        OH[rbase + cw] = hh; OL[rbase + cw] = ll;
        split_pair(o_[jq][2]*inv1, o_[jq][3]*inv1, hh, ll);
        OH[rbase + 8*768 + cw] = hh; OL[rbase + 8*768 + cw] = ll;
    }
}

// ---------------- launch ----------------
extern "C" void kernel_launch(void* const* d_in, const int* in_sizes, int n_in,
                              void* d_out, int out_size)
{
    (void)in_sizes; (void)n_in; (void)out_size;
    const float* hs  = (const float*)d_in[0];
    const float* ehs = (const float*)d_in[1];
    const float* wq  = (const float*)d_in[2];  const float* bq  = (const float*)d_in[3];
    const float* wk  = (const float*)d_in[4];  const float* bk  = (const float*)d_in[5];
    const float* wv  = (const float*)d_in[6];  const float* bv  = (const float*)d_in[7];
    const float* awq = (const float*)d_in[8];  const float* abq = (const float*)d_in[9];
    const float* awk = (const float*)d_in[10]; const float* abk = (const float*)d_in[11];
    const float* awv = (const float*)d_in[12]; const float* abv = (const float*)d_in[13];
    const float* wo  = (const float*)d_in[14]; const float* bo  = (const float*)d_in[15];
    const float* wao = (const float*)d_in[16]; const float* bao = (const float*)d_in[17];
    float* out = (float*)d_out;

    float *q, *k, *v, *mq, *sq, *mk, *sk, *ps, *pss;
    uint4 *kf, *vf, *wp;
    uint32_t *hsh, *hsl, *esh, *esl, *aoh, *aol, *eoh, *eol;
    cudaGetSymbolAddress((void**)&q,  g_q);
    cudaGetSymbolAddress((void**)&k,  g_k);
    cudaGetSymbolAddress((void**)&v,  g_v);
    cudaGetSymbolAddress((void**)&mq, g_mq);
    cudaGetSymbolAddress((void**)&sq, g_sq);
    cudaGetSymbolAddress((void**)&mk, g_mk);
    cudaGetSymbolAddress((void**)&sk, g_sk);
    cudaGetSymbolAddress((void**)&ps, g_ps);
    cudaGetSymbolAddress((void**)&pss, g_pss);
    cudaGetSymbolAddress((void**)&kf, g_kf);
    cudaGetSymbolAddress((void**)&vf, g_vf);
    cudaGetSymbolAddress((void**)&wp, g_wp);
    cudaGetSymbolAddress((void**)&hsh, g_hsh);
    cudaGetSymbolAddress((void**)&hsl, g_hsl);
    cudaGetSymbolAddress((void**)&esh, g_esh);
    cudaGetSymbolAddress((void**)&esl, g_esl);
    cudaGetSymbolAddress((void**)&aoh, g_aoh);
    cudaGetSymbolAddress((void**)&aol, g_aol);
    cudaGetSymbolAddress((void**)&eoh, g_eoh);
    cudaGetSymbolAddress((void**)&eol, g_eol);

    static int attr_set = 0;
    if (!attr_set) {
        cudaFuncSetAttribute(gemm_qkv, cudaFuncAttributeMaxDynamicSharedMemorySize, GEMM_SMEM);
        cudaFuncSetAttribute(gemm_out, cudaFuncAttributeMaxDynamicSharedMemorySize, GEMM_SMEM);
        cudaFuncSetAttribute(attn_bf3, cudaFuncAttributeMaxDynamicSharedMemorySize, AT_SMEM);
        attr_set = 1;
    }

    conv_a<<<6144, 256>>>(hs,  hsh, hsl, 4096*384);
    conv_a<<<1536, 256>>>(ehs, esh, esl, 1024*384);
    conv_wp<<<dim3(12, 48, 8), 256>>>(wq, wk, wv, awq, awk, awv, wo, wao, wp);

    gemm_qkv<<<dim3(6, 32, 3), 1024, GEMM_SMEM>>>(
        hsh, hsl, wp, 0, bq, bk, bv, q, k, v,
        1024, LQ, LK, LK, 0, 0, 0);
    gemm_qkv<<<dim3(6, 8, 3), 1024, GEMM_SMEM>>>(
        esh, esl, wp, 3, abq, abk, abv, q, k, v,
        256, LQ, LK, LK, 1024, 2048, 2048);

    stats_part<<<dim3(96, 4, 2), 256>>>(q, k, ps, pss);
    stats_fin<<<dim3(96, 2), 64>>>(ps, pss, mq, sq, mk, sk);

    adain_q_kernel<<<3072, 256>>>(q, mq, sq);
    convert_k<<<dim3(20, 96), 256>>>(k, mk, sk, kf);
    convert_v<<<dim3(20, 96), 256>>>(v, vf);

    attn_bf3<<<dim3(10, 24, 4), 256, AT_SMEM>>>(q, kf, vf, aoh, aol, eoh, eol);

    gemm_out<<<dim3(6, 32, 2), 1024, GEMM_SMEM>>>(
        aoh, aol, eoh, eol, wp, 6, bo, bao,
        out, out + (size_t)4096*1536);
}

// round 16
// speedup vs baseline: 1.3348x; 1.0028x over previous
#include <cuda_runtime.h>
#include <cuda_bf16.h>
#include <math.h>
#include <stdint.h>

#define NUM_H 24
#define LQ 1280
#define LK 2304

// ---------------- scratch (device globals; no allocations) ----------------
__device__ float g_q[4*24*1280*64];      // (B,H,LQ,64)
__device__ float g_k[4*24*2304*64];
__device__ float g_v[4*24*2304*64];
__device__ float g_mq[6144], g_sq[6144], g_mk[6144], g_sk[6144];
__device__ float g_ps[2*96*4*64], g_pss[2*96*4*64];
__device__ uint4 g_kf[96*36*1024];
__device__ uint4 g_vf[96*36*1024];
__device__ uint32_t g_hsh[4096*768], g_hsl[4096*768];
__device__ uint32_t g_esh[1024*768], g_esl[1024*768];
__device__ uint32_t g_aoh[4096*768], g_aol[4096*768];
__device__ uint32_t g_eoh[1024*768], g_eol[1024*768];
__device__ uint4 g_wp[8*12*48*1024];

// ---------------- bf16 helpers ----------------
__device__ __forceinline__ void split_pair(float x, float y, uint32_t &hi, uint32_t &lo){
    __nv_bfloat162 hv = __floats2bfloat162_rn(x, y);
    hi = *reinterpret_cast<uint32_t*>(&hv);
    float rx = x - __low2float(hv);
    float ry = y - __high2float(hv);
    __nv_bfloat162 lv = __floats2bfloat162_rn(rx, ry);
    lo = *reinterpret_cast<uint32_t*>(&lv);
}

__device__ __forceinline__ void mma16(float* c, const uint32_t* a, uint32_t b0, uint32_t b1){
    asm volatile("mma.sync.aligned.m16n8k16.row.col.f32.bf16.bf16.f32 "
        "{%0,%1,%2,%3},{%4,%5,%6,%7},{%8,%9},{%0,%1,%2,%3};"
        : "+f"(c[0]),"+f"(c[1]),"+f"(c[2]),"+f"(c[3])
        : "r"(a[0]),"r"(a[1]),"r"(a[2]),"r"(a[3]),"r"(b0),"r"(b1));
}

__device__ __forceinline__ void ldsm4(uint32_t* r, uint32_t addr){
    asm volatile("ldmatrix.sync.aligned.m8n8.x4.shared.b16 {%0,%1,%2,%3}, [%4];"
        : "=r"(r[0]),"=r"(r[1]),"=r"(r[2]),"=r"(r[3]) : "r"(addr));
}

__device__ __forceinline__ void cp16(uint32_t saddr, const void* gptr){
    asm volatile("cp.async.cg.shared.global [%0], [%1], 16;" :: "r"(saddr), "l"(gptr));
}

// ===== split-bf16 GEMM: 128x256 tile, BK=32, 1024 threads, 4-stage ==========
#define GSTG 49152u
#define GEMM_SMEM (4*49152)    // 196608 B

__device__ __forceinline__ void gemm_core(
    const uint32_t* __restrict__ Ah, const uint32_t* __restrict__ Al,
    const uint4* __restrict__ Bp0, const uint4* __restrict__ Bp1,
    const float* __restrict__ bias, float* __restrict__ out,
    int heads_mode, int S_rows, int L, int s_off,
    int row0, int colblk0, uint32_t* sm)
{
    const int tid = threadIdx.x, lane = tid & 31, wrp = tid >> 5;
    const int g = lane >> 2, t = lane & 3;
    const int wm = wrp >> 3;
    const int wnl = wrp & 7;
    const int j = wnl >> 2;
    const int wn4 = wnl & 3;

    float acc[2][4][4];
    #pragma unroll
    for (int i=0;i<2;i++)
        #pragma unroll
        for (int jj=0;jj<4;jj++)
            #pragma unroll
            for (int r=0;r<4;r++) acc[i][jj][r]=0.f;

    const uint32_t sbase = (uint32_t)__cvta_generic_to_shared(sm);
    uint32_t a_off[2][2];
    #pragma unroll
    for (int mt=0; mt<2; mt++){
        int r = wm*32 + mt*16 + ((lane>>3)&1)*8 + (lane&7);
        int swz = (r>>1)&3;
        #pragma unroll
        for (int s=0; s<2; s++){
            int u = s*2 + (lane>>4);
            a_off[mt][s] = (uint32_t)(r*64 + ((u ^ swz)<<4));
        }
    }
    uint32_t b_slot[2][4];
    #pragma unroll
    for (int s=0; s<2; s++)
        #pragma unroll
        for (int nt=0; nt<4; nt++){
            int ntg = wn4*4 + nt;
            int lp = ((g*4+t) ^ (g>>1)) ^ ((ntg&1)<<2);
            b_slot[s][nt] = (uint32_t)(j*1024 + (s*16+ntg)*32 + lp);
        }

    const uint32_t aunit = (uint32_t)(tid & 511);
    const uint32_t ar = aunit >> 2, au = aunit & 3;
    const uint32_t a_so = (tid < 512 ? 0u : 8192u) + ar*64 + ((au ^ ((ar>>1)&3))<<4);
    const uint32_t* Asrc = (tid < 512) ? Ah : Al;

#define STAGE(tk_, st_) { \
    uint32_t sb = sbase + (uint32_t)(st_)*GSTG; \
    cp16(sb + a_so, Asrc + (size_t)(row0+ar)*768 + (uint32_t)(tk_)*16u + au*4); \
    cp16(sb + 16384u + (uint32_t)tid*16u, Bp0 + (size_t)(tk_)*1024 + tid); \
    cp16(sb + 32768u + (uint32_t)tid*16u, Bp1 + (size_t)(tk_)*1024 + tid); \
    asm volatile("cp.async.commit_group;" ::: "memory"); }

    STAGE(0, 0);
    STAGE(1, 1);
    STAGE(2, 2);

    const int nT = 48;
    for (int tk=0; tk<nT; tk++){
        const int st = tk & 3;
        const int rem = nT - 1 - tk;
        if (rem >= 2)      asm volatile("cp.async.wait_group 2;" ::: "memory");
        else if (rem == 1) asm volatile("cp.async.wait_group 1;" ::: "memory");
        else               asm volatile("cp.async.wait_group 0;" ::: "memory");
        __syncthreads();
        const uint32_t bufb = sbase + (uint32_t)st*GSTG;
        const uint4* Bs = (const uint4*)(sm + st*12288 + 4096);
        #pragma unroll
        for (int s=0;s<2;s++){
            uint32_t ah[2][4], al[2][4];
            #pragma unroll
            for (int mt=0;mt<2;mt++){
                ldsm4(ah[mt], bufb + a_off[mt][s]);
                ldsm4(al[mt], bufb + 8192u + a_off[mt][s]);
            }
            #pragma unroll
            for (int nt=0;nt<4;nt++){
                uint4 kw = Bs[b_slot[s][nt]];
                #pragma unroll
                for (int mt=0;mt<2;mt++){
                    mma16(acc[mt][nt], ah[mt], kw.x, kw.y);
                    mma16(acc[mt][nt], ah[mt], kw.z, kw.w);
                    mma16(acc[mt][nt], al[mt], kw.x, kw.y);
                }
            }
        }
        if (tk+3 < nT) { STAGE(tk+3, (tk+3)&3); }
    }
#undef STAGE

    #pragma unroll
    for (int mt=0;mt<2;mt++){
        int m0r = row0 + wm*32 + mt*16 + g;
        #pragma unroll
        for (int nt=0;nt<4;nt++){
            int c = (colblk0 + j)*128 + wn4*32 + nt*8 + t*2;
            float b0v = bias[c], b1v = bias[c+1];
            float2 v0 = make_float2(acc[mt][nt][0]+b0v, acc[mt][nt][1]+b1v);
            float2 v1 = make_float2(acc[mt][nt][2]+b0v, acc[mt][nt][3]+b1v);
            if (!heads_mode){
                *(float2*)&out[(size_t)m0r*1536 + c]     = v0;
                *(float2*)&out[(size_t)(m0r+8)*1536 + c] = v1;
            } else {
                int hh = c >> 6, hd = c & 63;
                int bb = m0r / S_rows, ss = m0r - bb*S_rows;
                *(float2*)&out[((size_t)(bb*NUM_H+hh)*L + s_off + ss)*64 + hd] = v0;
                int m1r = m0r + 8;
                int bb1 = m1r / S_rows, ss1 = m1r - bb1*S_rows;
                *(float2*)&out[((size_t)(bb1*NUM_H+hh)*L + s_off + ss1)*64 + hd] = v1;
            }
        }
    }
}

// merged QKV: y<32 hidden rows (M=4096), y>=32 encoder rows (M=1024)
__global__ void __launch_bounds__(1024, 1) gemm_qkv(
    const uint32_t* __restrict__ Hh, const uint32_t* __restrict__ Hl,
    const uint32_t* __restrict__ Eh, const uint32_t* __restrict__ El,
    const uint4* __restrict__ WP,
    const float* __restrict__ bq, const float* __restrict__ bk, const float* __restrict__ bv,
    const float* __restrict__ abq, const float* __restrict__ abk, const float* __restrict__ abv,
    float* __restrict__ q, float* __restrict__ k, float* __restrict__ v)
{
    extern __shared__ uint32_t sm[];
    const int z = blockIdx.z;
    const bool enc = (blockIdx.y >= 32);
    const uint32_t* Ah = enc ? Eh : Hh;
    const uint32_t* Al = enc ? El : Hl;
    const float* bi = enc ? ((z==0)? abq : (z==1)? abk : abv)
                          : ((z==0)? bq  : (z==1)? bk  : bv);
    float* out = (z==0)? q : (z==1)? k : v;
    int L = (z==0)? LQ : LK;
    int soff = enc ? ((z==0)? 1024 : 2048) : 0;
    int S_rows = enc ? 256 : 1024;
    int row0 = (enc ? (blockIdx.y - 32) : blockIdx.y) * 128;
    const uint4* Bp0 = WP + (size_t)(((enc?3:0)+z)*12 + blockIdx.x*2)*48*1024;
    gemm_core(Ah, Al, Bp0, Bp0 + 48*1024, bi, out, 1, S_rows, L, soff,
              row0, blockIdx.x*2, sm);
}

__global__ void __launch_bounds__(1024, 1) gemm_out(
    const uint32_t* __restrict__ A0h, const uint32_t* __restrict__ A0l,
    const uint32_t* __restrict__ A1h, const uint32_t* __restrict__ A1l,
    const uint4* __restrict__ WP, int widx0,
    const float* __restrict__ b0, const float* __restrict__ b1,
    float* __restrict__ o0, float* __restrict__ o1)
{
    extern __shared__ uint32_t sm[];
    const int z = blockIdx.z;
    if (z == 1 && blockIdx.y >= 8) return;
    const uint4* Bp0 = WP + (size_t)((widx0+z)*12 + blockIdx.x*2)*48*1024;
    gemm_core((z==0)? A0h : A1h, (z==0)? A0l : A1l, Bp0, Bp0 + 48*1024,
              (z==0)? b0 : b1, (z==0)? o0 : o1,
              0, 0, 0, 0, blockIdx.y*128, blockIdx.x*2, sm);
}

// ---------------- operand pre-conversion ----------------
__global__ void __launch_bounds__(256) conv_a(
    const float* __restrict__ x, uint32_t* __restrict__ hi, uint32_t* __restrict__ lo, int n4)
{
    int i = blockIdx.x*256 + threadIdx.x;
    if (i >= n4) return;
    float4 f = ((const float4*)x)[i];
    uint2 h, l;
    split_pair(f.x, f.y, h.x, l.x);
    split_pair(f.z, f.w, h.y, l.y);
    ((uint2*)hi)[i] = h; ((uint2*)lo)[i] = l;
}

__global__ void __launch_bounds__(256) conv_wp(
    const float* w0, const float* w1, const float* w2, const float* w3,
    const float* w4, const float* w5, const float* w6, const float* w7,
    uint4* __restrict__ wp)
{
    __shared__ float sw[32][129];
    const int cb = blockIdx.x, tk = blockIdx.y, z = blockIdx.z;
    const float* W = (z==0)?w0:(z==1)?w1:(z==2)?w2:(z==3)?w3:(z==4)?w4:(z==5)?w5:(z==6)?w6:w7;
    const int tid = threadIdx.x;
    #pragma unroll
    for (int i=0;i<4;i++){
        int e = tid + i*256;
        int r = e>>5, c4 = (e&31)*4;
        float4 f = *(const float4*)&W[(size_t)(tk*32+r)*1536 + cb*128 + c4];
        sw[r][c4]=f.x; sw[r][c4+1]=f.y; sw[r][c4+2]=f.z; sw[r][c4+3]=f.w;
    }
    __syncthreads();
    uint4* dst = wp + (size_t)((z*12+cb)*48 + tk)*1024;
    #pragma unroll
    for (int i=0;i<4;i++){
        int slot = tid + i*256;
        int idx32 = slot>>5, lp = slot&31;
        int bs = idx32>>4, ntg = idx32&15;
        int base = lp ^ ((ntg&1)<<2);
        int gg = base>>2, bt = (base&3) ^ (gg>>1);
        int n = ntg*8 + gg;
        int k0 = bs*16 + 2*bt;
        uint4 w4;
        split_pair(sw[k0][n],   sw[k0+1][n], w4.x, w4.z);
        split_pair(sw[k0+8][n], sw[k0+9][n], w4.y, w4.w);
        dst[slot] = w4;
    }
}

// ---------------- two-phase stats ----------------
__global__ void __launch_bounds__(256) stats_part(
    const float* __restrict__ q, const float* __restrict__ k,
    float* __restrict__ ps, float* __restrict__ pss)
{
    const int bh = blockIdx.x, part = blockIdx.y, z = blockIdx.z;
    const int tx = threadIdx.x & 63;
    const int ty = threadIdx.x >> 6;
    const float* p = (z ? k : q) + (size_t)bh * (z ? LK : LQ) * 64;
    float s = 0.f, ss = 0.f;
    for (int i = part*256 + ty; i < part*256 + 256; i += 4) {
        float v = p[(size_t)i*64 + tx];
        s += v; ss += v*v;
    }
    __shared__ float sh1[4][64], sh2[4][64];
    sh1[ty][tx] = s; sh2[ty][tx] = ss;
    __syncthreads();
    if (ty == 0) {
        int o = ((z*96+bh)*4+part)*64 + tx;
        ps [o] = sh1[0][tx]+sh1[1][tx]+sh1[2][tx]+sh1[3][tx];
        pss[o] = sh2[0][tx]+sh2[1][tx]+sh2[2][tx]+sh2[3][tx];
    }
}

__global__ void __launch_bounds__(64) stats_fin(
    const float* __restrict__ ps, const float* __restrict__ pss,
    float* __restrict__ mq, float* __restrict__ sq,
    float* __restrict__ mk, float* __restrict__ sk)
{
    const int bh = blockIdx.x, z = blockIdx.y, tx = threadIdx.x;
    float s = 0.f, ss = 0.f;
    #pragma unroll
    for (int p=0;p<4;p++){
        s  += ps [((z*96+bh)*4+p)*64 + tx];
        ss += pss[((z*96+bh)*4+p)*64 + tx];
    }
    float m = s * (1.0f/1024.0f);
    float var = (ss - 1024.0f*m*m) * (1.0f/1023.0f);
    (z ? mk : mq)[bh*64+tx] = m;
    (z ? sk : sq)[bh*64+tx] = sqrtf(var + 1e-5f);
}

// ---------------- merged convert K/V: tiles {0..15, 32..35}, z: 0=K 1=V -----
__global__ void __launch_bounds__(256) convert_kv(
    const float* __restrict__ k, const float* __restrict__ v,
    const float* __restrict__ mk, const float* __restrict__ sk,
    uint4* __restrict__ kf, uint4* __restrict__ vf)
{
    const int x = blockIdx.x, bh = blockIdx.y, z = blockIdx.z;
    const int kt = (x < 16) ? x : x + 16;
    const int b = bh / 24, h = bh - b*24;
    const bool style = (z == 0) && (b & 1) && (kt < 16);

    __shared__ float sK[64][65];
    __shared__ float pa[64], pc[64];
    const int tid = threadIdx.x;
    const float* src = (z ? v : k) + ((size_t)bh*LK + kt*64)*64;

    if (style && tid < 64){
        int sbh = (b-1)*24 + h;
        float a = sk[sbh*64+tid] / sk[bh*64+tid];
        pa[tid] = a;
        pc[tid] = mk[sbh*64+tid] - mk[bh*64+tid]*a;
    }
    __syncthreads();
    #pragma unroll
    for (int i=0;i<16;i++){
        int e = tid + i*256;
        float xv = src[e];
        if (style) xv = fmaf(xv, pa[e&63], pc[e&63]);
        sK[e>>6][e&63] = xv;
    }
    __syncthreads();
    if (z == 0){
        uint4* dst = kf + ((size_t)bh*36 + kt)*1024;
        #pragma unroll
        for (int i=0;i<4;i++){
            int slot = tid + i*256;
            int lane = slot & 31, nt = (slot>>5)&7, s = slot>>8;
            int g = lane>>2, t = lane&3;
            int kv = nt*8+g, d0 = 16*s+2*t;
            uint4 w4;
            split_pair(sK[kv][d0],   sK[kv][d0+1], w4.x, w4.z);
            split_pair(sK[kv][d0+8], sK[kv][d0+9], w4.y, w4.w);
            dst[slot] = w4;
        }
    } else {
        uint4* dst = vf + ((size_t)bh*36 + kt)*1024;
        #pragma unroll
        for (int i=0;i<4;i++){
            int slot = tid + i*256;
            int lane = slot & 31, jn = (slot>>5)&7, s2 = slot>>8;
            int g = lane>>2, t = lane&3;
            int d = jn*8+g, r0 = 16*s2+2*t;
            uint4 w4;
            split_pair(sK[r0][d],   sK[r0+1][d], w4.x, w4.z);
            split_pair(sK[r0+8][d], sK[r0+9][d], w4.y, w4.w);
            dst[slot] = w4;
        }
    }
}

// ================= flash attention: inline Q styling, max-free softmax ======
// Q styling applies ONLY to hidden q-rows (qt<8); encoder queries pass through.
#define AT_SMEM (2*2048*16)

__global__ void __launch_bounds__(256, 2) attn_bf3(
    const float* __restrict__ Q,
    const float* __restrict__ mq, const float* __restrict__ sq,
    const uint4* __restrict__ KF, const uint4* __restrict__ VF,
    uint32_t* __restrict__ AOH, uint32_t* __restrict__ AOL,
    uint32_t* __restrict__ EOH, uint32_t* __restrict__ EOL)
{
    extern __shared__ uint4 sm4[];
    __shared__ float pa[64], pc[64];
    const int tid = threadIdx.x, lane = tid & 31, w = tid >> 5;
    const int g = lane >> 2, t = lane & 3;
    const int qt = blockIdx.x, h = blockIdx.y, b = blockIdx.z;
    const bool odd = (b & 1);
    const int nkt = odd ? 36 : 20;
    const size_t bh = (size_t)b*NUM_H + h;
    const float* Qg = Q + (bh*LQ + (size_t)qt*128) * 64;
    const uint4* Kg = KF + bh*36*1024;
    const uint4* Vg = VF + bh*36*1024;
    const uint4* KgS = Kg - (size_t)24*36*1024;
    const uint4* VgS = Vg - (size_t)24*36*1024;
    const uint32_t smem_base = (uint32_t)__cvta_generic_to_shared(sm4);
    const float QSCALE = 0.125f * 1.44269504088896f;
    const bool styleq = odd && (qt < 8);   // hidden q-rows only

    if (tid < 64){
        if (styleq){
            int sbh = (int)bh - 24;
            float a = sq[sbh*64+tid] / sq[bh*64+tid];
            pa[tid] = a * QSCALE;
            pc[tid] = (mq[sbh*64+tid] - mq[bh*64+tid]*a) * QSCALE;
        } else {
            pa[tid] = QSCALE; pc[tid] = 0.f;
        }
    }

#define STAGE(jj_, buf_) { \
    int kt_; const uint4 *kb_, *vb_; \
    if (odd){ \
        if ((jj_) >= 16 && (jj_) < 32){ kt_ = (jj_) - 16; kb_ = KgS; vb_ = VgS; } \
        else { kt_ = (jj_); kb_ = Kg; vb_ = Vg; } \
    } else { \
        kt_ = ((jj_) < 16) ? (jj_) : (jj_) + 16; kb_ = Kg; vb_ = Vg; \
    } \
    uint32_t sb = smem_base + (buf_)*32768u; \
    const uint4* kp = kb_ + (size_t)kt_*1024 + tid; \
    const uint4* vp = vb_ + (size_t)kt_*1024 + tid; \
    _Pragma("unroll") \
    for (int i_=0;i_<4;i_++){ \
        cp16(sb + (uint32_t)(tid + i_*256)*16u,           kp + i_*256); \
        cp16(sb + 16384u + (uint32_t)(tid + i_*256)*16u,  vp + i_*256); \
    } \
    asm volatile("cp.async.commit_group;"); }

    STAGE(0, 0);
    __syncthreads();   // pa/pc visible

    uint32_t qh[4][4], ql[4][4];
    {
        const int r0 = w*16 + g;
        #pragma unroll
        for (int s=0;s<4;s++){
            int d0 = 16*s + 2*t;
            float2 x00 = *(const float2*)&Qg[(size_t)r0*64 + d0];
            float2 x10 = *(const float2*)&Qg[(size_t)(r0+8)*64 + d0];
            float2 x01 = *(const float2*)&Qg[(size_t)r0*64 + d0 + 8];
            float2 x11 = *(const float2*)&Qg[(size_t)(r0+8)*64 + d0 + 8];
            float a0 = pa[d0],   c0 = pc[d0];
            float a1 = pa[d0+1], c1 = pc[d0+1];
            float a8 = pa[d0+8], c8 = pc[d0+8];
            float a9 = pa[d0+9], c9 = pc[d0+9];
            split_pair(fmaf(x00.x,a0,c0), fmaf(x00.y,a1,c1), qh[s][0], ql[s][0]);
            split_pair(fmaf(x10.x,a0,c0), fmaf(x10.y,a1,c1), qh[s][1], ql[s][1]);
            split_pair(fmaf(x01.x,a8,c8), fmaf(x01.y,a9,c9), qh[s][2], ql[s][2]);
            split_pair(fmaf(x11.x,a8,c8), fmaf(x11.y,a9,c9), qh[s][3], ql[s][3]);
        }
    }

    float o_[8][4];
    #pragma unroll
    for (int jq=0;jq<8;jq++){ o_[jq][0]=0.f; o_[jq][1]=0.f; o_[jq][2]=0.f; o_[jq][3]=0.f; }
    float l0s=0.f, l1s=0.f;

    for (int jj=0; jj<nkt; jj++){
        asm volatile("cp.async.wait_group 0;");
        __syncthreads();
        if (jj+1 < nkt) { STAGE(jj+1, (jj+1)&1); }

        const uint4* Kt = sm4 + (jj&1)*2048;
        const uint4* Vt = Kt + 1024;
        const float padd = (!odd && jj < 16) ? 1.0f : 0.0f;

        float s_[8][4];
        #pragma unroll
        for (int jq=0;jq<8;jq++){ s_[jq][0]=0.f; s_[jq][1]=0.f; s_[jq][2]=0.f; s_[jq][3]=0.f; }
        #pragma unroll
        for (int s=0;s<4;s++)
            #pragma unroll
            for (int nt=0;nt<8;nt++){
                uint4 kw = Kt[(s*8+nt)*32 + lane];
                mma16(s_[nt], qh[s], kw.x, kw.y);
                mma16(s_[nt], qh[s], kw.z, kw.w);
                mma16(s_[nt], ql[s], kw.x, kw.y);
            }

        #pragma unroll
        for (int jq=0;jq<8;jq++){
            s_[jq][0]=exp2f(s_[jq][0]+padd); s_[jq][1]=exp2f(s_[jq][1]+padd);
            s_[jq][2]=exp2f(s_[jq][2]+padd); s_[jq][3]=exp2f(s_[jq][3]+padd);
            l0s += s_[jq][0]+s_[jq][1];
            l1s += s_[jq][2]+s_[jq][3];
        }

        uint32_t ph[4][4], pl[4][4];
        #pragma unroll
        for (int s2=0;s2<4;s2++){
            split_pair(s_[2*s2][0],   s_[2*s2][1],   ph[s2][0], pl[s2][0]);
            split_pair(s_[2*s2][2],   s_[2*s2][3],   ph[s2][1], pl[s2][1]);
            split_pair(s_[2*s2+1][0], s_[2*s2+1][1], ph[s2][2], pl[s2][2]);
            split_pair(s_[2*s2+1][2], s_[2*s2+1][3], ph[s2][3], pl[s2][3]);
        }

        #pragma unroll
        for (int s2=0;s2<4;s2++)
            #pragma unroll
            for (int jq=0;jq<8;jq++){
                uint4 vw = Vt[(s2*8+jq)*32 + lane];
                mma16(o_[jq], ph[s2], vw.x, vw.y);
                mma16(o_[jq], ph[s2], vw.z, vw.w);
                mma16(o_[jq], pl[s2], vw.x, vw.y);
            }
    }
#undef STAGE

    l0s += __shfl_xor_sync(0xffffffffu, l0s, 1);
    l0s += __shfl_xor_sync(0xffffffffu, l0s, 2);
    l1s += __shfl_xor_sync(0xffffffffu, l1s, 1);
    l1s += __shfl_xor_sync(0xffffffffu, l1s, 2);
    float inv0 = 1.0f / l0s, inv1 = 1.0f / l1s;
    int q0 = qt*128 + w*16 + g;

    uint32_t *OH, *OL;
    size_t rbase;
    if (q0 < 1024){ OH = AOH; OL = AOL; rbase = (size_t)(b*1024 + q0)*768; }
    else          { OH = EOH; OL = EOL; rbase = (size_t)(b*256 + q0 - 1024)*768; }
    #pragma unroll
    for (int jq=0;jq<8;jq++){
        int cw = h*32 + jq*4 + t;
        uint32_t hh, ll;
        split_pair(o_[jq][0]*inv0, o_[jq][1]*inv0, hh, ll);
        OH[rbase + cw] = hh; OL[rbase + cw] = ll;
        split_pair(o_[jq][2]*inv1, o_[jq][3]*inv1, hh, ll);
        OH[rbase + 8*768 + cw] = hh; OL[rbase + 8*768 + cw] = ll;
    }
}

// ---------------- launch ----------------
extern "C" void kernel_launch(void* const* d_in, const int* in_sizes, int n_in,
                              void* d_out, int out_size)
{
    (void)in_sizes; (void)n_in; (void)out_size;
    const float* hs  = (const float*)d_in[0];
    const float* ehs = (const float*)d_in[1];
    const float* wq  = (const float*)d_in[2];  const float* bq  = (const float*)d_in[3];
    const float* wk  = (const float*)d_in[4];  const float* bk  = (const float*)d_in[5];
    const float* wv  = (const float*)d_in[6];  const float* bv  = (const float*)d_in[7];
    const float* awq = (const float*)d_in[8];  const float* abq = (const float*)d_in[9];
    const float* awk = (const float*)d_in[10]; const float* abk = (const float*)d_in[11];
    const float* awv = (const float*)d_in[12]; const float* abv = (const float*)d_in[13];
    const float* wo  = (const float*)d_in[14]; const float* bo  = (const float*)d_in[15];
    const float* wao = (const float*)d_in[16]; const float* bao = (const float*)d_in[17];
    float* out = (float*)d_out;

    float *q, *k, *v, *mq, *sq, *mk, *sk, *ps, *pss;
    uint4 *kf, *vf, *wp;
    uint32_t *hsh, *hsl, *esh, *esl, *aoh, *aol, *eoh, *eol;
    cudaGetSymbolAddress((void**)&q,  g_q);
    cudaGetSymbolAddress((void**)&k,  g_k);
    cudaGetSymbolAddress((void**)&v,  g_v);
    cudaGetSymbolAddress((void**)&mq, g_mq);
    cudaGetSymbolAddress((void**)&sq, g_sq);
    cudaGetSymbolAddress((void**)&mk, g_mk);
    cudaGetSymbolAddress((void**)&sk, g_sk);
    cudaGetSymbolAddress((void**)&ps, g_ps);
    cudaGetSymbolAddress((void**)&pss, g_pss);
    cudaGetSymbolAddress((void**)&kf, g_kf);
    cudaGetSymbolAddress((void**)&vf, g_vf);
    cudaGetSymbolAddress((void**)&wp, g_wp);
    cudaGetSymbolAddress((void**)&hsh, g_hsh);
    cudaGetSymbolAddress((void**)&hsl, g_hsl);
    cudaGetSymbolAddress((void**)&esh, g_esh);
    cudaGetSymbolAddress((void**)&esl, g_esl);
    cudaGetSymbolAddress((void**)&aoh, g_aoh);
    cudaGetSymbolAddress((void**)&aol, g_aol);
    cudaGetSymbolAddress((void**)&eoh, g_eoh);
    cudaGetSymbolAddress((void**)&eol, g_eol);

    static int attr_set = 0;
    if (!attr_set) {
        cudaFuncSetAttribute(gemm_qkv, cudaFuncAttributeMaxDynamicSharedMemorySize, GEMM_SMEM);
        cudaFuncSetAttribute(gemm_out, cudaFuncAttributeMaxDynamicSharedMemorySize, GEMM_SMEM);
        cudaFuncSetAttribute(attn_bf3, cudaFuncAttributeMaxDynamicSharedMemorySize, AT_SMEM);
        attr_set = 1;
    }

    conv_a<<<6144, 256>>>(hs,  hsh, hsl, 4096*384);
    conv_a<<<1536, 256>>>(ehs, esh, esl, 1024*384);
    conv_wp<<<dim3(12, 48, 8), 256>>>(wq, wk, wv, awq, awk, awv, wo, wao, wp);

    gemm_qkv<<<dim3(6, 40, 3), 1024, GEMM_SMEM>>>(
        hsh, hsl, esh, esl, wp,
        bq, bk, bv, abq, abk, abv, q, k, v);

    stats_part<<<dim3(96, 4, 2), 256>>>(q, k, ps, pss);
    stats_fin<<<dim3(96, 2), 64>>>(ps, pss, mq, sq, mk, sk);

    convert_kv<<<dim3(20, 96, 2), 256>>>(k, v, mk, sk, kf, vf);

    attn_bf3<<<dim3(10, 24, 4), 256, AT_SMEM>>>(q, mq, sq, kf, vf, aoh, aol, eoh, eol);

    gemm_out<<<dim3(6, 32, 2), 1024, GEMM_SMEM>>>(
        aoh, aol, eoh, eol, wp, 6, bo, bao,
        out, out + (size_t)4096*1536);
}